// round 11
// baseline (speedup 1.0000x reference)
#include <cuda_runtime.h>
#include <cuda_bf16.h>
#include <cstdint>
#include <math.h>

#define TOKENS 4096
#define DMODEL 4096
#define HIDDEN 10922
#define HPADN  11008   // hidden padded to 256 (output cols for gate & up)
#define HPADK  10944   // hidden padded to 64; also activation buffer stride (mult of 4)
#define NSTAGE 3       // pipeline stages, each K=64: A 16KB + B 32KB = 48KB
#define STAGE_BYTES 49152

// ---------------- device scratch (all bf16 frag-packed for HMMA) ----------------
__device__ __align__(256) __nv_bfloat16 g_Xbf[(size_t)TOKENS * DMODEL];   // A frags
__device__ __align__(256) __nv_bfloat16 g_Gbf[(size_t)HPADN * DMODEL];    // B frags
__device__ __align__(256) __nv_bfloat16 g_Ubf[(size_t)HPADN * DMODEL];    // B frags
__device__ __align__(256) __nv_bfloat16 g_Dbf[(size_t)DMODEL * HPADK];    // B frags
__device__ __align__(256) __nv_bfloat16 g_Abf[(size_t)TOKENS * HPADK];    // A frags
__device__ __align__(16) float g_gate[(size_t)TOKENS * HPADK];   // padded stride
__device__ __align__(16) float g_up  [(size_t)TOKENS * HPADK];   // padded stride
__device__ float g_absmax[8];   // 0:x 1:wg 2:wu 3:wd 4:gate 5:up 6:act

// ---------------- helpers ----------------
__device__ __forceinline__ void atomicMaxPosF(float* a, float v) {
    atomicMax((unsigned int*)a, __float_as_uint(v));
}
__device__ __forceinline__ float quant_round(float x, float s) {
    float r = rintf(__fdiv_rn(x, s));
    return fminf(fmaxf(r, -127.0f), 127.0f);
}
__device__ __forceinline__ float get_scale(int slot) {
    return fmaxf(__fdiv_rn(g_absmax[slot], 127.0f), 1e-8f);
}
__device__ __forceinline__ uint32_t smem_u32(const void* p) {
    uint32_t a;
    asm("{ .reg .u64 t; cvta.to.shared.u64 t, %1; cvt.u32.u64 %0, t; }" : "=r"(a) : "l"(p));
    return a;
}
__device__ __forceinline__ uint32_t bf2(float a, float b, float s) {
    __nv_bfloat16 lo = __float2bfloat16_rn(quant_round(a, s));
    __nv_bfloat16 hi = __float2bfloat16_rn(quant_round(b, s));
    return (uint32_t)__bfloat16_as_ushort(lo) | ((uint32_t)__bfloat16_as_ushort(hi) << 16);
}
// load 32 consecutive floats; p at least 8B-aligned; a16: 16B-aligned
__device__ __forceinline__ void load32(const float* __restrict__ p, float* f, bool a16) {
    if (a16) {
        #pragma unroll
        for (int q = 0; q < 8; q++) *(float4*)&f[q * 4] = __ldg((const float4*)p + q);
    } else {
        #pragma unroll
        for (int q = 0; q < 16; q++) *(float2*)&f[q * 2] = __ldg((const float2*)p + q);
    }
}
#define CP_ASYNC16(dst, src) \
    asm volatile("cp.async.cg.shared.global [%0], [%1], 16;" :: "r"(dst), "l"(src))
#define CP_COMMIT() asm volatile("cp.async.commit_group;")
#define CP_WAIT(n)  asm volatile("cp.async.wait_group %0;" :: "n"(n))

#define HMMA(acc, a, b) \
    asm volatile("mma.sync.aligned.m16n8k16.row.col.f32.bf16.bf16.f32 " \
        "{%0,%1,%2,%3}, {%4,%5,%6,%7}, {%8,%9}, {%0,%1,%2,%3};" \
        : "+f"((acc)[0]), "+f"((acc)[1]), "+f"((acc)[2]), "+f"((acc)[3]) \
        : "r"((a).x), "r"((a).y), "r"((a).z), "r"((a).w), "r"((b).x), "r"((b).y))

__global__ void k_init() { if (threadIdx.x < 8) g_absmax[threadIdx.x] = 0.0f; }

// ---- one kernel: absmax of all 4 inputs ----
__device__ __forceinline__ void absmax_seg(const float* __restrict__ t, size_t n4, int slot) {
    float m = 0.0f;
    size_t i = (size_t)blockIdx.x * blockDim.x + threadIdx.x;
    size_t st = (size_t)gridDim.x * blockDim.x;
    const float4* t4 = (const float4*)t;
    for (; i < n4; i += st) {
        float4 v = t4[i];
        m = fmaxf(m, fmaxf(fmaxf(fabsf(v.x), fabsf(v.y)), fmaxf(fabsf(v.z), fabsf(v.w))));
    }
    #pragma unroll
    for (int o = 16; o; o >>= 1) m = fmaxf(m, __shfl_xor_sync(0xffffffffu, m, o));
    if ((threadIdx.x & 31) == 0) atomicMaxPosF(&g_absmax[slot], m);
}
__global__ void k_absmax_all(const float* __restrict__ x, const float* __restrict__ wg,
                             const float* __restrict__ wu, const float* __restrict__ wd) {
    absmax_seg(x,  (size_t)TOKENS * DMODEL / 4, 0);
    absmax_seg(wg, (size_t)HIDDEN * DMODEL / 4, 1);
    absmax_seg(wu, (size_t)HIDDEN * DMODEL / 4, 2);
    absmax_seg(wd, (size_t)DMODEL * HIDDEN / 4, 3);
}

// ======== bf16 HMMA pack bodies (m16n8k16) ========
// A frag layout: [mtile][k16][m16][lane]x16B (regs a0..a3)
__device__ __forceinline__ void packA_body(const float* __restrict__ src,
                                           uint32_t* __restrict__ d32, float s,
                                           int rows, int nK32, int srcStride, int Kvalid,
                                           size_t gid, size_t gstride) {
    const int nK16 = nK32 * 2;
    size_t total = (size_t)rows * nK32;
    for (size_t i = gid; i < total; i += gstride) {
        int row = (int)(i % rows);
        int k32 = (int)(i / rows);
        int kb0 = k32 * 32;
        float f[32];
        if (kb0 + 32 <= Kvalid) {
            load32(src + (size_t)row * srcStride + kb0, f, true);
        } else {
            #pragma unroll
            for (int j = 0; j < 32; j++)
                f[j] = (kb0 + j < Kvalid) ? __ldg(src + (size_t)row * srcStride + kb0 + j) : 0.0f;
        }
        int mtile = row >> 7, rr = row & 127;
        int m16 = rr >> 4, g = rr & 7, rb = (rr >> 3) & 1;
        #pragma unroll
        for (int kh = 0; kh < 2; kh++) {
            int k16 = k32 * 2 + kh;
            uint32_t* base = d32 + (size_t)(mtile * nK16 + k16) * 1024 + m16 * 128 + 16 * g;
            const float* fk = f + kh * 16;
            #pragma unroll
            for (int t = 0; t < 4; t++) {
                base[4 * t + rb]     = bf2(fk[2 * t],     fk[2 * t + 1], s);
                base[4 * t + rb + 2] = bf2(fk[8 + 2 * t], fk[9 + 2 * t], s);
            }
        }
    }
}

// B frag layout: [ntile128][k16][n8][lane]x8B (regs b0,b1); 8 contiguous words per thread
__device__ __forceinline__ void packB_body(const float* __restrict__ src,
                                           uint32_t* __restrict__ d32, float s,
                                           int rows, int nK32, int srcStride,
                                           int Nvalid, int Kvalid,
                                           size_t gid, size_t gstride) {
    const int nK16 = nK32 * 2;
    size_t total = (size_t)rows * nK32;
    for (size_t i = gid; i < total; i += gstride) {
        int n = (int)(i % rows);
        int k32 = (int)(i / rows);
        int kb0 = k32 * 32;
        float f[32];
        if (n < Nvalid) {
            size_t off = (size_t)n * srcStride + kb0;
            if (kb0 + 32 <= Kvalid) {
                load32(src + off, f, (off & 3) == 0);
            } else {
                #pragma unroll
                for (int j = 0; j < 32; j++)
                    f[j] = (kb0 + j < Kvalid) ? __ldg(src + off + j) : 0.0f;
            }
        } else {
            #pragma unroll
            for (int j = 0; j < 32; j++) f[j] = 0.0f;
        }
        int ntile = n >> 7, nr = n & 127;
        int n8 = nr >> 3, g = nr & 7;
        #pragma unroll
        for (int kh = 0; kh < 2; kh++) {
            int k16 = k32 * 2 + kh;
            uint32_t* base = d32 + (size_t)(ntile * nK16 + k16) * 1024 + n8 * 64 + 8 * g;
            const float* fk = f + kh * 16;
            uint32_t out[8];
            #pragma unroll
            for (int t = 0; t < 4; t++) {
                out[2 * t]     = bf2(fk[2 * t],     fk[2 * t + 1], s);
                out[2 * t + 1] = bf2(fk[8 + 2 * t], fk[9 + 2 * t], s);
            }
            *(uint4*)base       = *(const uint4*)&out[0];
            *(uint4*)(base + 4) = *(const uint4*)&out[4];
        }
    }
}

__global__ void k_packA_bf16(const float* __restrict__ src, __nv_bfloat16* __restrict__ dst,
                             int rows, int nK32, int srcStride, int Kvalid, int slot) {
    packA_body(src, (uint32_t*)dst, get_scale(slot), rows, nK32, srcStride, Kvalid,
               (size_t)blockIdx.x * blockDim.x + threadIdx.x,
               (size_t)gridDim.x * blockDim.x);
}
__global__ void k_packB_bf16(const float* __restrict__ src, __nv_bfloat16* __restrict__ dst,
                             int rows, int nK32, int srcStride, int Nvalid, int Kvalid, int slot) {
    packB_body(src, (uint32_t*)dst, get_scale(slot), rows, nK32, srcStride, Nvalid, Kvalid,
               (size_t)blockIdx.x * blockDim.x + threadIdx.x,
               (size_t)gridDim.x * blockDim.x);
}

// merged: packA(x) + packB(wg) in one launch (so gate GEMM is launch index 3)
__global__ void k_pack_xg(const float* __restrict__ x, __nv_bfloat16* __restrict__ dx,
                          const float* __restrict__ wg, __nv_bfloat16* __restrict__ dg) {
    size_t gid = (size_t)blockIdx.x * blockDim.x + threadIdx.x;
    size_t gstride = (size_t)gridDim.x * blockDim.x;
    packA_body(x, (uint32_t*)dx, get_scale(0), TOKENS, DMODEL / 32, DMODEL, DMODEL,
               gid, gstride);
    packB_body(wg, (uint32_t*)dg, get_scale(1), HPADN, DMODEL / 32, DMODEL, HIDDEN, DMODEL,
               gid, gstride);
}

// ---- act = silu(q(gate)) * q(up) in place into gate; absmax -> slot 6 ----
__global__ void k_act(float* __restrict__ gate, const float* __restrict__ up, size_t n4) {
    float sg = get_scale(4), su = get_scale(5);
    float m = 0.0f;
    size_t i = (size_t)blockIdx.x * blockDim.x + threadIdx.x;
    size_t st = (size_t)gridDim.x * blockDim.x;
    float4* g4 = (float4*)gate;
    const float4* u4 = (const float4*)up;
    for (; i < n4; i += st) {
        float4 gv = g4[i];
        float4 uv = u4[i];
        float* gp = (float*)&gv;
        const float* uq4 = (const float*)&uv;
        #pragma unroll
        for (int k = 0; k < 4; k++) {
            float gq = quant_round(gp[k], sg) * sg;
            float uq = quant_round(uq4[k], su) * su;
            float a = gq * (1.0f / (1.0f + expf(-gq))) * uq;
            gp[k] = a;
            m = fmaxf(m, fabsf(a));
        }
        g4[i] = gv;
    }
    #pragma unroll
    for (int o = 16; o; o >>= 1) m = fmaxf(m, __shfl_xor_sync(0xffffffffu, m, o));
    if ((threadIdx.x & 31) == 0) atomicMaxPosF(&g_absmax[6], m);
}

// ---------------- bf16 HMMA GEMM: 128x256 CTA tile, 8 warps (64x64 warp tile) ----------------
// One stage = 48KB = K64: A 16KB (4 k16-chunks) + B 2x16KB (two 128-row tiles).
// A tile stride = KS*16384; B per-128-tile total = 2*KS*16384... = nK16*4096 bytes.
template<bool DO_AMAX>
__global__ void __launch_bounds__(256, 1)
k_gemm(const __nv_bfloat16* __restrict__ A, const __nv_bfloat16* __restrict__ B,
       const float* __restrict__ bias, float* __restrict__ C,
       int nK32, int Nvalid, int Cstride, int sa, int sb, int amax_slot) {
    extern __shared__ __align__(16) char smem[];   // NSTAGE * 48KB
    const int tid = threadIdx.x, lane = tid & 31, wid = tid >> 5;
    const int wm = wid >> 2, wn = wid & 3;         // warp grid 2 x 4, warp tile 64 x 64
    const int mtile = blockIdx.y, ntile = blockIdx.x;   // ntile covers 256 cols = 2 B-tiles

    const int KS = nK32 >> 1;                       // stages (K=64 each); nK32 always even
    const size_t nK16b = (size_t)nK32 * 2 * 4096;   // bytes per 128-row B tile
    const char* Ag  = (const char*)A + (size_t)mtile * KS * 16384;
    const char* Bg0 = (const char*)B + (size_t)(ntile * 2)     * nK16b;
    const char* Bg1 = (const char*)B + (size_t)(ntile * 2 + 1) * nK16b;

    float acc[4][8][4];
    #pragma unroll
    for (int i = 0; i < 4; i++)
        #pragma unroll
        for (int j = 0; j < 8; j++)
            #pragma unroll
            for (int r = 0; r < 4; r++) acc[i][j][r] = 0.0f;

    const uint32_t sbase = smem_u32(smem);
    const uint32_t co = (uint32_t)tid * 16u;

    auto issue = [&](int st) {
        uint32_t buf = sbase + (uint32_t)(st % NSTAGE) * (uint32_t)STAGE_BYTES;
        const char* ga = Ag  + (size_t)st * 16384;
        const char* g0 = Bg0 + (size_t)st * 16384;
        const char* g1 = Bg1 + (size_t)st * 16384;
        #pragma unroll
        for (int w = 0; w < 4; w++) {
            CP_ASYNC16(buf + co + w * 4096u,           ga + co + w * 4096u);
            CP_ASYNC16(buf + co + w * 4096u + 16384u,  g0 + co + w * 4096u);
            CP_ASYNC16(buf + co + w * 4096u + 32768u,  g1 + co + w * 4096u);
        }
    };

    #pragma unroll
    for (int p = 0; p < NSTAGE - 1; p++) {
        if (p < KS) issue(p);
        CP_COMMIT();
    }

    const int tile_b = wn >> 1;            // which B 128-tile this warp reads
    const int n8base = (wn & 1) * 8;       // n8 offset within that tile

    for (int c = 0; c < KS; c++) {
        CP_WAIT(NSTAGE - 2);
        __syncthreads();
        if (c + NSTAGE - 1 < KS) issue(c + NSTAGE - 1);
        CP_COMMIT();

        const char* bufA = smem + (c % NSTAGE) * STAGE_BYTES;
        const char* bufB = bufA + 16384 + tile_b * 16384;
        #pragma unroll
        for (int kk = 0; kk < 4; kk++) {      // four k16 chunks per stage
            int4 av[4];
            int2 bv[8];
            #pragma unroll
            for (int i = 0; i < 4; i++)
                av[i] = *(const int4*)(bufA + kk * 4096 + (((wm * 4 + i) * 32 + lane) << 4));
            #pragma unroll
            for (int j = 0; j < 8; j++)
                bv[j] = *(const int2*)(bufB + kk * 4096 + (((n8base + j) * 32 + lane) << 3));
            #pragma unroll
            for (int i = 0; i < 4; i++)
                #pragma unroll
                for (int j = 0; j < 8; j++)
                    HMMA(acc[i][j], av[i], bv[j]);
        }
    }

    // epilogue: scale + bias (+ absmax)
    const float sab = get_scale(sa) * get_scale(sb);
    const int g = lane >> 2, t = lane & 3;
    float vmax = 0.0f;
    #pragma unroll
    for (int i = 0; i < 4; i++) {
        int row0 = mtile * 128 + wm * 64 + i * 16 + g;
        #pragma unroll
        for (int j = 0; j < 8; j++) {
            int col = ntile * 256 + wn * 64 + j * 8 + t * 2;
            if (col < Nvalid) {
                float b0 = __ldg(&bias[col]), b1 = __ldg(&bias[col + 1]);
                float2 v0, v1;
                v0.x = fmaf(acc[i][j][0], sab, b0);
                v0.y = fmaf(acc[i][j][1], sab, b1);
                v1.x = fmaf(acc[i][j][2], sab, b0);
                v1.y = fmaf(acc[i][j][3], sab, b1);
                *(float2*)(C + (size_t)row0 * Cstride + col) = v0;
                *(float2*)(C + (size_t)(row0 + 8) * Cstride + col) = v1;
                if (DO_AMAX)
                    vmax = fmaxf(vmax, fmaxf(fmaxf(fabsf(v0.x), fabsf(v0.y)),
                                             fmaxf(fabsf(v1.x), fabsf(v1.y))));
            }
        }
    }
    if (DO_AMAX) {
        #pragma unroll
        for (int o = 16; o; o >>= 1) vmax = fmaxf(vmax, __shfl_xor_sync(0xffffffffu, vmax, o));
        if (lane == 0) atomicMaxPosF(&g_absmax[amax_slot], vmax);
    }
}

// ---------------- launch ----------------
extern "C" void kernel_launch(void* const* d_in, const int* in_sizes, int n_in,
                              void* d_out, int out_size) {
    (void)in_sizes; (void)n_in; (void)out_size;
    const float* x  = (const float*)d_in[0];
    const float* wg = (const float*)d_in[1];
    const float* wu = (const float*)d_in[2];
    const float* wd = (const float*)d_in[3];
    const float* bg = (const float*)d_in[4];
    const float* bu = (const float*)d_in[5];
    const float* bd = (const float*)d_in[6];
    float* out = (float*)d_out;

    __nv_bfloat16 *pXbf, *pGbf, *pUbf, *pDbf, *pAbf;
    float *pGate, *pUp;
    cudaGetSymbolAddress((void**)&pXbf, g_Xbf);
    cudaGetSymbolAddress((void**)&pGbf, g_Gbf);
    cudaGetSymbolAddress((void**)&pUbf, g_Ubf);
    cudaGetSymbolAddress((void**)&pDbf, g_Dbf);
    cudaGetSymbolAddress((void**)&pAbf, g_Abf);
    cudaGetSymbolAddress((void**)&pGate, g_gate);
    cudaGetSymbolAddress((void**)&pUp, g_up);

    cudaFuncSetAttribute(k_gemm<true>,  cudaFuncAttributeMaxDynamicSharedMemorySize, NSTAGE * STAGE_BYTES);
    cudaFuncSetAttribute(k_gemm<false>, cudaFuncAttributeMaxDynamicSharedMemorySize, NSTAGE * STAGE_BYTES);

    const int RT = 256;
    const int nK32g = DMODEL / 32;   // 128
    const int nK32d = HPADK / 32;    // 342

    dim3 g1(HPADN / 256, TOKENS / 128);   // 43 x 32
    dim3 g2(DMODEL / 256, TOKENS / 128);  // 16 x 32

    // ncu captures launch index 3 -> gate GEMM there
    k_init<<<1, 8>>>();                                                        // 0
    k_absmax_all<<<2048, RT>>>(x, wg, wu, wd);                                 // 1
    k_pack_xg<<<4096, RT>>>(x, pXbf, wg, pGbf);                                // 2
    k_gemm<true><<<g1, 256, NSTAGE * STAGE_BYTES>>>(                           // 3  <- ncu capture
        pXbf, pGbf, bg, pGate, nK32g, HIDDEN, HPADK, 0, 1, 4);
    k_packB_bf16<<<((size_t)HPADN * nK32g + RT - 1) / RT, RT>>>(               // 4
        wu, pUbf, HPADN, nK32g, DMODEL, HIDDEN, DMODEL, 2);
    k_gemm<true><<<g1, 256, NSTAGE * STAGE_BYTES>>>(                           // 5
        pXbf, pUbf, bu, pUp, nK32g, HIDDEN, HPADK, 0, 2, 5);
    k_packB_bf16<<<((size_t)DMODEL * nK32d + RT - 1) / RT, RT>>>(              // 6
        wd, pDbf, DMODEL, nK32d, HIDDEN, DMODEL, HIDDEN, 3);
    k_act<<<2048, RT>>>(pGate, pUp, (size_t)TOKENS * HPADK / 4);               // 7
    k_packA_bf16<<<((size_t)TOKENS * nK32d + RT - 1) / RT, RT>>>(              // 8
        pGate, pAbf, TOKENS, nK32d, HPADK, HPADK, 6);
    k_gemm<false><<<g2, 256, NSTAGE * STAGE_BYTES>>>(                          // 9
        pAbf, pDbf, bd, out, nK32d, DMODEL, DMODEL, 6, 3, -1);
}

// round 12
// speedup vs baseline: 1.7204x; 1.7204x over previous
#include <cuda_runtime.h>
#include <cuda_bf16.h>
#include <cstdint>
#include <math.h>

#define TOKENS 4096
#define DMODEL 4096
#define HIDDEN 10922
#define HPADN  11008   // hidden padded to 128 (output cols for gate & up)
#define HPADK  10944   // hidden padded to 64; also activation buffer stride (mult of 4)
#define NSPLIT 86      // gate tiles 0..85, up tiles 86..171 in fused B buffer
#define NSTAGE 3       // pipeline stages, each K=64 (A 16KB + B 16KB = 32KB)
#define STAGE_BYTES 32768

// ---------------- device scratch (all bf16 frag-packed for HMMA) ----------------
__device__ __align__(256) __nv_bfloat16 g_Xbf[(size_t)TOKENS * DMODEL];       // A frags
__device__ __align__(256) __nv_bfloat16 g_GUbf[2 * (size_t)HPADN * DMODEL];   // B frags: wg | wu
__device__ __align__(256) __nv_bfloat16 g_Dbf[(size_t)DMODEL * HPADK];        // B frags
__device__ __align__(256) __nv_bfloat16 g_Abf[(size_t)TOKENS * HPADK];        // A frags
__device__ __align__(16) float g_gate[(size_t)TOKENS * HPADK];   // padded stride
__device__ __align__(16) float g_up  [(size_t)TOKENS * HPADK];   // padded stride
__device__ float g_absmax[8];   // 0:x 1:wg 2:wu 3:wd 4:gate 5:up 6:act

// ---------------- helpers ----------------
__device__ __forceinline__ void atomicMaxPosF(float* a, float v) {
    atomicMax((unsigned int*)a, __float_as_uint(v));
}
__device__ __forceinline__ float quant_round(float x, float s) {
    float r = rintf(__fdiv_rn(x, s));
    return fminf(fmaxf(r, -127.0f), 127.0f);
}
__device__ __forceinline__ float get_scale(int slot) {
    return fmaxf(__fdiv_rn(g_absmax[slot], 127.0f), 1e-8f);
}
__device__ __forceinline__ uint32_t smem_u32(const void* p) {
    uint32_t a;
    asm("{ .reg .u64 t; cvta.to.shared.u64 t, %1; cvt.u32.u64 %0, t; }" : "=r"(a) : "l"(p));
    return a;
}
__device__ __forceinline__ uint32_t bf2(float a, float b, float s) {
    __nv_bfloat16 lo = __float2bfloat16_rn(quant_round(a, s));
    __nv_bfloat16 hi = __float2bfloat16_rn(quant_round(b, s));
    return (uint32_t)__bfloat16_as_ushort(lo) | ((uint32_t)__bfloat16_as_ushort(hi) << 16);
}
// load 32 consecutive floats; p at least 8B-aligned; a16: 16B-aligned
__device__ __forceinline__ void load32(const float* __restrict__ p, float* f, bool a16) {
    if (a16) {
        #pragma unroll
        for (int q = 0; q < 8; q++) *(float4*)&f[q * 4] = __ldg((const float4*)p + q);
    } else {
        #pragma unroll
        for (int q = 0; q < 16; q++) *(float2*)&f[q * 2] = __ldg((const float2*)p + q);
    }
}
#define CP_ASYNC16(dst, src) \
    asm volatile("cp.async.cg.shared.global [%0], [%1], 16;" :: "r"(dst), "l"(src))
#define CP_COMMIT() asm volatile("cp.async.commit_group;")
#define CP_WAIT(n)  asm volatile("cp.async.wait_group %0;" :: "n"(n))

#define HMMA(acc, a, b) \
    asm volatile("mma.sync.aligned.m16n8k16.row.col.f32.bf16.bf16.f32 " \
        "{%0,%1,%2,%3}, {%4,%5,%6,%7}, {%8,%9}, {%0,%1,%2,%3};" \
        : "+f"((acc)[0]), "+f"((acc)[1]), "+f"((acc)[2]), "+f"((acc)[3]) \
        : "r"((a).x), "r"((a).y), "r"((a).z), "r"((a).w), "r"((b).x), "r"((b).y))

__global__ void k_init() { if (threadIdx.x < 8) g_absmax[threadIdx.x] = 0.0f; }

// ---- one kernel: absmax of all 4 inputs ----
__device__ __forceinline__ void absmax_seg(const float* __restrict__ t, size_t n4, int slot) {
    float m = 0.0f;
    size_t i = (size_t)blockIdx.x * blockDim.x + threadIdx.x;
    size_t st = (size_t)gridDim.x * blockDim.x;
    const float4* t4 = (const float4*)t;
    for (; i < n4; i += st) {
        float4 v = t4[i];
        m = fmaxf(m, fmaxf(fmaxf(fabsf(v.x), fabsf(v.y)), fmaxf(fabsf(v.z), fabsf(v.w))));
    }
    #pragma unroll
    for (int o = 16; o; o >>= 1) m = fmaxf(m, __shfl_xor_sync(0xffffffffu, m, o));
    if ((threadIdx.x & 31) == 0) atomicMaxPosF(&g_absmax[slot], m);
}
__global__ void k_absmax_all(const float* __restrict__ x, const float* __restrict__ wg,
                             const float* __restrict__ wu, const float* __restrict__ wd) {
    absmax_seg(x,  (size_t)TOKENS * DMODEL / 4, 0);
    absmax_seg(wg, (size_t)HIDDEN * DMODEL / 4, 1);
    absmax_seg(wu, (size_t)HIDDEN * DMODEL / 4, 2);
    absmax_seg(wd, (size_t)DMODEL * HIDDEN / 4, 3);
}

// ======== bf16 HMMA pack bodies (m16n8k16) ========
// A frag layout: [mtile][k16][m16][lane]x16B (regs a0..a3)
__device__ __forceinline__ void packA_body(const float* __restrict__ src,
                                           uint32_t* __restrict__ d32, float s,
                                           int rows, int nK32, int srcStride, int Kvalid,
                                           size_t gid, size_t gstride) {
    const int nK16 = nK32 * 2;
    size_t total = (size_t)rows * nK32;
    for (size_t i = gid; i < total; i += gstride) {
        int row = (int)(i % rows);
        int k32 = (int)(i / rows);
        int kb0 = k32 * 32;
        float f[32];
        if (kb0 + 32 <= Kvalid) {
            load32(src + (size_t)row * srcStride + kb0, f, true);
        } else {
            #pragma unroll
            for (int j = 0; j < 32; j++)
                f[j] = (kb0 + j < Kvalid) ? __ldg(src + (size_t)row * srcStride + kb0 + j) : 0.0f;
        }
        int mtile = row >> 7, rr = row & 127;
        int m16 = rr >> 4, g = rr & 7, rb = (rr >> 3) & 1;
        #pragma unroll
        for (int kh = 0; kh < 2; kh++) {
            int k16 = k32 * 2 + kh;
            uint32_t* base = d32 + (size_t)(mtile * nK16 + k16) * 1024 + m16 * 128 + 16 * g;
            const float* fk = f + kh * 16;
            #pragma unroll
            for (int t = 0; t < 4; t++) {
                base[4 * t + rb]     = bf2(fk[2 * t],     fk[2 * t + 1], s);
                base[4 * t + rb + 2] = bf2(fk[8 + 2 * t], fk[9 + 2 * t], s);
            }
        }
    }
}

// B frag layout: [ntile128][k16][n8][lane]x8B (regs b0,b1); 8 contiguous words per thread
__device__ __forceinline__ void packB_body(const float* __restrict__ src,
                                           uint32_t* __restrict__ d32, float s,
                                           int rows, int nK32, int srcStride,
                                           int Nvalid, int Kvalid,
                                           size_t gid, size_t gstride) {
    const int nK16 = nK32 * 2;
    size_t total = (size_t)rows * nK32;
    for (size_t i = gid; i < total; i += gstride) {
        int n = (int)(i % rows);
        int k32 = (int)(i / rows);
        int kb0 = k32 * 32;
        float f[32];
        if (n < Nvalid) {
            size_t off = (size_t)n * srcStride + kb0;
            if (kb0 + 32 <= Kvalid) {
                load32(src + off, f, (off & 3) == 0);
            } else {
                #pragma unroll
                for (int j = 0; j < 32; j++)
                    f[j] = (kb0 + j < Kvalid) ? __ldg(src + off + j) : 0.0f;
            }
        } else {
            #pragma unroll
            for (int j = 0; j < 32; j++) f[j] = 0.0f;
        }
        int ntile = n >> 7, nr = n & 127;
        int n8 = nr >> 3, g = nr & 7;
        #pragma unroll
        for (int kh = 0; kh < 2; kh++) {
            int k16 = k32 * 2 + kh;
            uint32_t* base = d32 + (size_t)(ntile * nK16 + k16) * 1024 + n8 * 64 + 8 * g;
            const float* fk = f + kh * 16;
            uint32_t out[8];
            #pragma unroll
            for (int t = 0; t < 4; t++) {
                out[2 * t]     = bf2(fk[2 * t],     fk[2 * t + 1], s);
                out[2 * t + 1] = bf2(fk[8 + 2 * t], fk[9 + 2 * t], s);
            }
            *(uint4*)base       = *(const uint4*)&out[0];
            *(uint4*)(base + 4) = *(const uint4*)&out[4];
        }
    }
}

__global__ void k_packA_bf16(const float* __restrict__ src, __nv_bfloat16* __restrict__ dst,
                             int rows, int nK32, int srcStride, int Kvalid, int slot) {
    packA_body(src, (uint32_t*)dst, get_scale(slot), rows, nK32, srcStride, Kvalid,
               (size_t)blockIdx.x * blockDim.x + threadIdx.x,
               (size_t)gridDim.x * blockDim.x);
}
__global__ void k_packB_bf16(const float* __restrict__ src, __nv_bfloat16* __restrict__ dst,
                             int rows, int nK32, int srcStride, int Nvalid, int Kvalid, int slot) {
    packB_body(src, (uint32_t*)dst, get_scale(slot), rows, nK32, srcStride, Nvalid, Kvalid,
               (size_t)blockIdx.x * blockDim.x + threadIdx.x,
               (size_t)gridDim.x * blockDim.x);
}

// merged: packA(x) + packB(wg) + packB(wu) in one launch (gate/up GEMM is launch index 3)
__global__ void k_pack_xgu(const float* __restrict__ x, __nv_bfloat16* __restrict__ dx,
                           const float* __restrict__ wg, const float* __restrict__ wu,
                           __nv_bfloat16* __restrict__ dgu) {
    size_t gid = (size_t)blockIdx.x * blockDim.x + threadIdx.x;
    size_t gstride = (size_t)gridDim.x * blockDim.x;
    packA_body(x, (uint32_t*)dx, get_scale(0), TOKENS, DMODEL / 32, DMODEL, DMODEL,
               gid, gstride);
    packB_body(wg, (uint32_t*)dgu, get_scale(1), HPADN, DMODEL / 32, DMODEL, HIDDEN, DMODEL,
               gid, gstride);
    packB_body(wu, (uint32_t*)(dgu + (size_t)HPADN * DMODEL), get_scale(2),
               HPADN, DMODEL / 32, DMODEL, HIDDEN, DMODEL, gid, gstride);
}

// ---- act = silu(q(gate)) * q(up) in place into gate; absmax -> slot 6 ----
__global__ void k_act(float* __restrict__ gate, const float* __restrict__ up, size_t n4) {
    float sg = get_scale(4), su = get_scale(5);
    float m = 0.0f;
    size_t i = (size_t)blockIdx.x * blockDim.x + threadIdx.x;
    size_t st = (size_t)gridDim.x * blockDim.x;
    float4* g4 = (float4*)gate;
    const float4* u4 = (const float4*)up;
    for (; i < n4; i += st) {
        float4 gv = g4[i];
        float4 uv = u4[i];
        float* gp = (float*)&gv;
        const float* uq4 = (const float*)&uv;
        #pragma unroll
        for (int k = 0; k < 4; k++) {
            float gq = quant_round(gp[k], sg) * sg;
            float uq = quant_round(uq4[k], su) * su;
            float a = gq * (1.0f / (1.0f + expf(-gq))) * uq;
            gp[k] = a;
            m = fmaxf(m, fabsf(a));
        }
        g4[i] = gv;
    }
    #pragma unroll
    for (int o = 16; o; o >>= 1) m = fmaxf(m, __shfl_xor_sync(0xffffffffu, m, o));
    if ((threadIdx.x & 31) == 0) atomicMaxPosF(&g_absmax[6], m);
}

// ---------------- bf16 HMMA GEMM (round-10 config: 128x128, 8 warps, 64x32 warp tile) ----------------
// One stage = 32KB = K64 (4 k16-chunks): A 16KB + B 16KB. Per-tile operand stride = KS*16384 bytes.
// DUAL: B holds gate tiles [0,NSPLIT) then up tiles [NSPLIT,2*NSPLIT); epilogue routes by ntile.
template<bool DUAL>
__global__ void __launch_bounds__(256, 2)
k_gemm(const __nv_bfloat16* __restrict__ A, const __nv_bfloat16* __restrict__ B,
       const float* __restrict__ bias0, const float* __restrict__ bias1,
       float* __restrict__ C0, float* __restrict__ C1,
       int nK32, int Nvalid, int Cstride, int sa, int sb0, int sb1) {
    extern __shared__ __align__(16) char smem[];   // NSTAGE * 32KB
    const int tid = threadIdx.x, lane = tid & 31, wid = tid >> 5;
    const int wm = wid >> 2, wn = wid & 3;         // warp grid 2 x 4 (64x32 warp tile)
    const int mtile = blockIdx.y, ntile = blockIdx.x;

    const int KS = nK32 >> 1;                       // stages (K=64 each); nK32 always even
    const char* Ag = (const char*)A + (size_t)mtile * KS * 16384;
    const char* Bg = (const char*)B + (size_t)ntile * KS * 16384;

    float acc[4][4][4];
    #pragma unroll
    for (int i = 0; i < 4; i++)
        #pragma unroll
        for (int j = 0; j < 4; j++)
            #pragma unroll
            for (int r = 0; r < 4; r++) acc[i][j][r] = 0.0f;

    const uint32_t sbase = smem_u32(smem);
    const uint32_t co = (uint32_t)tid * 16u;

    auto issue = [&](int st) {
        uint32_t buf = sbase + (uint32_t)(st % NSTAGE) * (uint32_t)STAGE_BYTES;
        const char* ga = Ag + (size_t)st * 16384;
        const char* gb = Bg + (size_t)st * 16384;
        #pragma unroll
        for (int w = 0; w < 4; w++) {
            CP_ASYNC16(buf + co + w * 4096u,          ga + co + w * 4096u);
            CP_ASYNC16(buf + co + w * 4096u + 16384u, gb + co + w * 4096u);
        }
    };

    #pragma unroll
    for (int p = 0; p < NSTAGE - 1; p++) {
        if (p < KS) issue(p);
        CP_COMMIT();
    }

    for (int c = 0; c < KS; c++) {
        CP_WAIT(NSTAGE - 2);
        __syncthreads();
        if (c + NSTAGE - 1 < KS) issue(c + NSTAGE - 1);
        CP_COMMIT();

        const char* bufA = smem + (c % NSTAGE) * STAGE_BYTES;
        const char* bufB = bufA + 16384;
        #pragma unroll
        for (int kk = 0; kk < 4; kk++) {      // four k16 chunks per stage
            int4 av[4];
            int2 bv[4];
            #pragma unroll
            for (int i = 0; i < 4; i++)
                av[i] = *(const int4*)(bufA + (((kk * 8 + wm * 4 + i) * 32 + lane) << 4));
            #pragma unroll
            for (int j = 0; j < 4; j++)
                bv[j] = *(const int2*)(bufB + (((kk * 16 + wn * 4 + j) * 32 + lane) << 3));
            #pragma unroll
            for (int i = 0; i < 4; i++)
                #pragma unroll
                for (int j = 0; j < 4; j++)
                    HMMA(acc[i][j], av[i], bv[j]);
        }
    }

    // epilogue: route output (DUAL: gate vs up region), scale + bias (+ absmax)
    const float* bias = bias0;
    float* C = C0;
    int sb = sb0, slot = 4, nt = ntile;
    if (DUAL && ntile >= NSPLIT) {
        bias = bias1; C = C1; sb = sb1; slot = 5; nt = ntile - NSPLIT;
    }
    const float sab = get_scale(sa) * get_scale(sb);
    const int g = lane >> 2, t = lane & 3;
    float vmax = 0.0f;
    #pragma unroll
    for (int i = 0; i < 4; i++) {
        int row0 = mtile * 128 + wm * 64 + i * 16 + g;
        #pragma unroll
        for (int j = 0; j < 4; j++) {
            int col = nt * 128 + wn * 32 + j * 8 + t * 2;
            if (col < Nvalid) {
                float b0 = __ldg(&bias[col]), b1 = __ldg(&bias[col + 1]);
                float2 v0, v1;
                v0.x = fmaf(acc[i][j][0], sab, b0);
                v0.y = fmaf(acc[i][j][1], sab, b1);
                v1.x = fmaf(acc[i][j][2], sab, b0);
                v1.y = fmaf(acc[i][j][3], sab, b1);
                *(float2*)(C + (size_t)row0 * Cstride + col) = v0;
                *(float2*)(C + (size_t)(row0 + 8) * Cstride + col) = v1;
                if (DUAL)
                    vmax = fmaxf(vmax, fmaxf(fmaxf(fabsf(v0.x), fabsf(v0.y)),
                                             fmaxf(fabsf(v1.x), fabsf(v1.y))));
            }
        }
    }
    if (DUAL) {
        #pragma unroll
        for (int o = 16; o; o >>= 1) vmax = fmaxf(vmax, __shfl_xor_sync(0xffffffffu, vmax, o));
        if (lane == 0) atomicMaxPosF(&g_absmax[slot], vmax);
    }
}

// ---------------- launch ----------------
extern "C" void kernel_launch(void* const* d_in, const int* in_sizes, int n_in,
                              void* d_out, int out_size) {
    (void)in_sizes; (void)n_in; (void)out_size;
    const float* x  = (const float*)d_in[0];
    const float* wg = (const float*)d_in[1];
    const float* wu = (const float*)d_in[2];
    const float* wd = (const float*)d_in[3];
    const float* bg = (const float*)d_in[4];
    const float* bu = (const float*)d_in[5];
    const float* bd = (const float*)d_in[6];
    float* out = (float*)d_out;

    __nv_bfloat16 *pXbf, *pGUbf, *pDbf, *pAbf;
    float *pGate, *pUp;
    cudaGetSymbolAddress((void**)&pXbf, g_Xbf);
    cudaGetSymbolAddress((void**)&pGUbf, g_GUbf);
    cudaGetSymbolAddress((void**)&pDbf, g_Dbf);
    cudaGetSymbolAddress((void**)&pAbf, g_Abf);
    cudaGetSymbolAddress((void**)&pGate, g_gate);
    cudaGetSymbolAddress((void**)&pUp, g_up);

    cudaFuncSetAttribute(k_gemm<true>,  cudaFuncAttributeMaxDynamicSharedMemorySize, NSTAGE * STAGE_BYTES);
    cudaFuncSetAttribute(k_gemm<false>, cudaFuncAttributeMaxDynamicSharedMemorySize, NSTAGE * STAGE_BYTES);

    const int RT = 256;
    const int nK32g = DMODEL / 32;   // 128
    const int nK32d = HPADK / 32;    // 342

    dim3 g1(2 * NSPLIT, TOKENS / 128);    // 172 x 32: fused gate|up
    dim3 g2(DMODEL / 128, TOKENS / 128);  // 32 x 32

    // ncu captures launch index 3 -> fused gate/up GEMM there
    k_init<<<1, 8>>>();                                                        // 0
    k_absmax_all<<<2048, RT>>>(x, wg, wu, wd);                                 // 1
    k_pack_xgu<<<4096, RT>>>(x, pXbf, wg, wu, pGUbf);                          // 2
    k_gemm<true><<<g1, 256, NSTAGE * STAGE_BYTES>>>(                           // 3  <- ncu capture
        pXbf, pGUbf, bg, bu, pGate, pUp, nK32g, HIDDEN, HPADK, 0, 1, 2);
    k_packB_bf16<<<((size_t)DMODEL * nK32d + RT - 1) / RT, RT>>>(              // 4
        wd, pDbf, DMODEL, nK32d, HIDDEN, DMODEL, HIDDEN, 3);
    k_act<<<2048, RT>>>(pGate, pUp, (size_t)TOKENS * HPADK / 4);               // 5
    k_packA_bf16<<<((size_t)TOKENS * nK32d + RT - 1) / RT, RT>>>(              // 6
        pGate, pAbf, TOKENS, nK32d, HPADK, HPADK, 6);
    k_gemm<false><<<g2, 256, NSTAGE * STAGE_BYTES>>>(                          // 7
        pAbf, pDbf, bd, bd, out, out, nK32d, DMODEL, DMODEL, 6, 3, 3);
}

// round 13
// speedup vs baseline: 1.7224x; 1.0012x over previous
#include <cuda_runtime.h>
#include <cuda_bf16.h>
#include <cstdint>
#include <math.h>

#define TOKENS 4096
#define DMODEL 4096
#define HIDDEN 10922
#define HPADN  11008   // hidden padded to 128 (output cols for gate & up)
#define HPADK  10944   // hidden padded to 64; also activation buffer stride (mult of 4)
#define NSPLIT 86      // gate tiles 0..85, up tiles 86..171 in fused B buffer
#define NSTAGE 3       // pipeline stages, each K=64 (A 16KB + B 16KB = 32KB)
#define STAGE_BYTES 32768

// ---------------- device scratch (all bf16 frag-packed for HMMA) ----------------
__device__ __align__(256) __nv_bfloat16 g_Xbf[(size_t)TOKENS * DMODEL];       // A frags
__device__ __align__(256) __nv_bfloat16 g_GUbf[2 * (size_t)HPADN * DMODEL];   // B frags: wg | wu
__device__ __align__(256) __nv_bfloat16 g_Dbf[(size_t)DMODEL * HPADK];        // B frags
__device__ __align__(256) __nv_bfloat16 g_Abf[(size_t)TOKENS * HPADK];        // A frags
__device__ __align__(16) float g_gate[(size_t)TOKENS * HPADK];   // padded stride
__device__ __align__(16) float g_up  [(size_t)TOKENS * HPADK];   // padded stride
__device__ float g_absmax[8];   // 0:x 1:wg 2:wu 3:wd 4:gate 5:up 6:act

// ---------------- helpers ----------------
__device__ __forceinline__ void atomicMaxPosF(float* a, float v) {
    atomicMax((unsigned int*)a, __float_as_uint(v));
}
__device__ __forceinline__ float quant_round(float x, float s) {
    float r = rintf(__fdiv_rn(x, s));
    return fminf(fmaxf(r, -127.0f), 127.0f);
}
__device__ __forceinline__ float get_scale(int slot) {
    return fmaxf(__fdiv_rn(g_absmax[slot], 127.0f), 1e-8f);
}
__device__ __forceinline__ uint32_t smem_u32(const void* p) {
    uint32_t a;
    asm("{ .reg .u64 t; cvta.to.shared.u64 t, %1; cvt.u32.u64 %0, t; }" : "=r"(a) : "l"(p));
    return a;
}
__device__ __forceinline__ uint32_t bf2(float a, float b, float s) {
    __nv_bfloat16 lo = __float2bfloat16_rn(quant_round(a, s));
    __nv_bfloat16 hi = __float2bfloat16_rn(quant_round(b, s));
    return (uint32_t)__bfloat16_as_ushort(lo) | ((uint32_t)__bfloat16_as_ushort(hi) << 16);
}
// load 32 consecutive floats; p at least 8B-aligned; a16: 16B-aligned
__device__ __forceinline__ void load32(const float* __restrict__ p, float* f, bool a16) {
    if (a16) {
        #pragma unroll
        for (int q = 0; q < 8; q++) *(float4*)&f[q * 4] = __ldg((const float4*)p + q);
    } else {
        #pragma unroll
        for (int q = 0; q < 16; q++) *(float2*)&f[q * 2] = __ldg((const float2*)p + q);
    }
}
#define CP_ASYNC16(dst, src) \
    asm volatile("cp.async.cg.shared.global [%0], [%1], 16;" :: "r"(dst), "l"(src))
#define CP_COMMIT() asm volatile("cp.async.commit_group;")
#define CP_WAIT(n)  asm volatile("cp.async.wait_group %0;" :: "n"(n))

#define HMMA(acc, a, b) \
    asm volatile("mma.sync.aligned.m16n8k16.row.col.f32.bf16.bf16.f32 " \
        "{%0,%1,%2,%3}, {%4,%5,%6,%7}, {%8,%9}, {%0,%1,%2,%3};" \
        : "+f"((acc)[0]), "+f"((acc)[1]), "+f"((acc)[2]), "+f"((acc)[3]) \
        : "r"((a).x), "r"((a).y), "r"((a).z), "r"((a).w), "r"((b).x), "r"((b).y))

__global__ void k_init() { if (threadIdx.x < 8) g_absmax[threadIdx.x] = 0.0f; }

// ---- one kernel: absmax of all 4 inputs ----
__device__ __forceinline__ void absmax_seg(const float* __restrict__ t, size_t n4, int slot) {
    float m = 0.0f;
    size_t i = (size_t)blockIdx.x * blockDim.x + threadIdx.x;
    size_t st = (size_t)gridDim.x * blockDim.x;
    const float4* t4 = (const float4*)t;
    for (; i < n4; i += st) {
        float4 v = t4[i];
        m = fmaxf(m, fmaxf(fmaxf(fabsf(v.x), fabsf(v.y)), fmaxf(fabsf(v.z), fabsf(v.w))));
    }
    #pragma unroll
    for (int o = 16; o; o >>= 1) m = fmaxf(m, __shfl_xor_sync(0xffffffffu, m, o));
    if ((threadIdx.x & 31) == 0) atomicMaxPosF(&g_absmax[slot], m);
}
__global__ void k_absmax_all(const float* __restrict__ x, const float* __restrict__ wg,
                             const float* __restrict__ wu, const float* __restrict__ wd) {
    absmax_seg(x,  (size_t)TOKENS * DMODEL / 4, 0);
    absmax_seg(wg, (size_t)HIDDEN * DMODEL / 4, 1);
    absmax_seg(wu, (size_t)HIDDEN * DMODEL / 4, 2);
    absmax_seg(wd, (size_t)DMODEL * HIDDEN / 4, 3);
}

// ======== bf16 HMMA pack bodies (m16n8k16) ========
// A frag layout: [mtile][k16][m16][lane]x16B (regs a0..a3)
__device__ __forceinline__ void packA_body(const float* __restrict__ src,
                                           uint32_t* __restrict__ d32, float s,
                                           int rows, int nK32, int srcStride, int Kvalid,
                                           size_t gid, size_t gstride) {
    const int nK16 = nK32 * 2;
    size_t total = (size_t)rows * nK32;
    for (size_t i = gid; i < total; i += gstride) {
        int row = (int)(i % rows);
        int k32 = (int)(i / rows);
        int kb0 = k32 * 32;
        float f[32];
        if (kb0 + 32 <= Kvalid) {
            load32(src + (size_t)row * srcStride + kb0, f, true);
        } else {
            #pragma unroll
            for (int j = 0; j < 32; j++)
                f[j] = (kb0 + j < Kvalid) ? __ldg(src + (size_t)row * srcStride + kb0 + j) : 0.0f;
        }
        int mtile = row >> 7, rr = row & 127;
        int m16 = rr >> 4, g = rr & 7, rb = (rr >> 3) & 1;
        #pragma unroll
        for (int kh = 0; kh < 2; kh++) {
            int k16 = k32 * 2 + kh;
            uint32_t* base = d32 + (size_t)(mtile * nK16 + k16) * 1024 + m16 * 128 + 16 * g;
            const float* fk = f + kh * 16;
            #pragma unroll
            for (int t = 0; t < 4; t++) {
                base[4 * t + rb]     = bf2(fk[2 * t],     fk[2 * t + 1], s);
                base[4 * t + rb + 2] = bf2(fk[8 + 2 * t], fk[9 + 2 * t], s);
            }
        }
    }
}

// B frag layout: [ntile128][k16][n8][lane]x8B (regs b0,b1); 8 contiguous words per thread
__device__ __forceinline__ void packB_body(const float* __restrict__ src,
                                           uint32_t* __restrict__ d32, float s,
                                           int rows, int nK32, int srcStride,
                                           int Nvalid, int Kvalid,
                                           size_t gid, size_t gstride) {
    const int nK16 = nK32 * 2;
    size_t total = (size_t)rows * nK32;
    for (size_t i = gid; i < total; i += gstride) {
        int n = (int)(i % rows);
        int k32 = (int)(i / rows);
        int kb0 = k32 * 32;
        float f[32];
        if (n < Nvalid) {
            size_t off = (size_t)n * srcStride + kb0;
            if (kb0 + 32 <= Kvalid) {
                load32(src + off, f, (off & 3) == 0);
            } else {
                #pragma unroll
                for (int j = 0; j < 32; j++)
                    f[j] = (kb0 + j < Kvalid) ? __ldg(src + off + j) : 0.0f;
            }
        } else {
            #pragma unroll
            for (int j = 0; j < 32; j++) f[j] = 0.0f;
        }
        int ntile = n >> 7, nr = n & 127;
        int n8 = nr >> 3, g = nr & 7;
        #pragma unroll
        for (int kh = 0; kh < 2; kh++) {
            int k16 = k32 * 2 + kh;
            uint32_t* base = d32 + (size_t)(ntile * nK16 + k16) * 1024 + n8 * 64 + 8 * g;
            const float* fk = f + kh * 16;
            uint32_t out[8];
            #pragma unroll
            for (int t = 0; t < 4; t++) {
                out[2 * t]     = bf2(fk[2 * t],     fk[2 * t + 1], s);
                out[2 * t + 1] = bf2(fk[8 + 2 * t], fk[9 + 2 * t], s);
            }
            *(uint4*)base       = *(const uint4*)&out[0];
            *(uint4*)(base + 4) = *(const uint4*)&out[4];
        }
    }
}

__global__ void k_packA_bf16(const float* __restrict__ src, __nv_bfloat16* __restrict__ dst,
                             int rows, int nK32, int srcStride, int Kvalid, int slot) {
    packA_body(src, (uint32_t*)dst, get_scale(slot), rows, nK32, srcStride, Kvalid,
               (size_t)blockIdx.x * blockDim.x + threadIdx.x,
               (size_t)gridDim.x * blockDim.x);
}
__global__ void k_packB_bf16(const float* __restrict__ src, __nv_bfloat16* __restrict__ dst,
                             int rows, int nK32, int srcStride, int Nvalid, int Kvalid, int slot) {
    packB_body(src, (uint32_t*)dst, get_scale(slot), rows, nK32, srcStride, Nvalid, Kvalid,
               (size_t)blockIdx.x * blockDim.x + threadIdx.x,
               (size_t)gridDim.x * blockDim.x);
}

// merged: packA(x) + packB(wg) + packB(wu) in one launch (gate/up GEMM is launch index 3)
__global__ void k_pack_xgu(const float* __restrict__ x, __nv_bfloat16* __restrict__ dx,
                           const float* __restrict__ wg, const float* __restrict__ wu,
                           __nv_bfloat16* __restrict__ dgu) {
    size_t gid = (size_t)blockIdx.x * blockDim.x + threadIdx.x;
    size_t gstride = (size_t)gridDim.x * blockDim.x;
    packA_body(x, (uint32_t*)dx, get_scale(0), TOKENS, DMODEL / 32, DMODEL, DMODEL,
               gid, gstride);
    packB_body(wg, (uint32_t*)dgu, get_scale(1), HPADN, DMODEL / 32, DMODEL, HIDDEN, DMODEL,
               gid, gstride);
    packB_body(wu, (uint32_t*)(dgu + (size_t)HPADN * DMODEL), get_scale(2),
               HPADN, DMODEL / 32, DMODEL, HIDDEN, DMODEL, gid, gstride);
}

// ---- act = silu(q(gate)) * q(up) in place into gate; absmax -> slot 6 ----
__global__ void k_act(float* __restrict__ gate, const float* __restrict__ up, size_t n4) {
    float sg = get_scale(4), su = get_scale(5);
    float m = 0.0f;
    size_t i = (size_t)blockIdx.x * blockDim.x + threadIdx.x;
    size_t st = (size_t)gridDim.x * blockDim.x;
    float4* g4 = (float4*)gate;
    const float4* u4 = (const float4*)up;
    for (; i < n4; i += st) {
        float4 gv = g4[i];
        float4 uv = u4[i];
        float* gp = (float*)&gv;
        const float* uq4 = (const float*)&uv;
        #pragma unroll
        for (int k = 0; k < 4; k++) {
            float gq = quant_round(gp[k], sg) * sg;
            float uq = quant_round(uq4[k], su) * su;
            float a = gq * (1.0f / (1.0f + expf(-gq))) * uq;
            gp[k] = a;
            m = fmaxf(m, fabsf(a));
        }
        g4[i] = gv;
    }
    #pragma unroll
    for (int o = 16; o; o >>= 1) m = fmaxf(m, __shfl_xor_sync(0xffffffffu, m, o));
    if ((threadIdx.x & 31) == 0) atomicMaxPosF(&g_absmax[6], m);
}

// ---------------- bf16 HMMA GEMM (128x128, 8 warps, 64x32 warp tile) ----------------
// One stage = 32KB = K64 (4 k16-chunks): A 16KB + B 16KB. Per-tile operand stride = KS*16384 bytes.
// Grid: blockIdx.x = mtile (FAST axis -> wave covers all m-tiles, few n-tiles:
//   B stripes hit DRAM once; A stays L2-resident), blockIdx.y = ntile.
// DUAL: B holds gate tiles [0,NSPLIT) then up tiles [NSPLIT,2*NSPLIT); epilogue routes by ntile.
template<bool DUAL>
__global__ void __launch_bounds__(256, 2)
k_gemm(const __nv_bfloat16* __restrict__ A, const __nv_bfloat16* __restrict__ B,
       const float* __restrict__ bias0, const float* __restrict__ bias1,
       float* __restrict__ C0, float* __restrict__ C1,
       int nK32, int Nvalid, int Cstride, int sa, int sb0, int sb1) {
    extern __shared__ __align__(16) char smem[];   // NSTAGE * 32KB
    const int tid = threadIdx.x, lane = tid & 31, wid = tid >> 5;
    const int wm = wid >> 2, wn = wid & 3;         // warp grid 2 x 4 (64x32 warp tile)
    const int mtile = blockIdx.x, ntile = blockIdx.y;   // m fastest for wave locality

    const int KS = nK32 >> 1;                       // stages (K=64 each); nK32 always even
    const char* Ag = (const char*)A + (size_t)mtile * KS * 16384;
    const char* Bg = (const char*)B + (size_t)ntile * KS * 16384;

    float acc[4][4][4];
    #pragma unroll
    for (int i = 0; i < 4; i++)
        #pragma unroll
        for (int j = 0; j < 4; j++)
            #pragma unroll
            for (int r = 0; r < 4; r++) acc[i][j][r] = 0.0f;

    const uint32_t sbase = smem_u32(smem);
    const uint32_t co = (uint32_t)tid * 16u;

    auto issue = [&](int st) {
        uint32_t buf = sbase + (uint32_t)(st % NSTAGE) * (uint32_t)STAGE_BYTES;
        const char* ga = Ag + (size_t)st * 16384;
        const char* gb = Bg + (size_t)st * 16384;
        #pragma unroll
        for (int w = 0; w < 4; w++) {
            CP_ASYNC16(buf + co + w * 4096u,          ga + co + w * 4096u);
            CP_ASYNC16(buf + co + w * 4096u + 16384u, gb + co + w * 4096u);
        }
    };

    #pragma unroll
    for (int p = 0; p < NSTAGE - 1; p++) {
        if (p < KS) issue(p);
        CP_COMMIT();
    }

    for (int c = 0; c < KS; c++) {
        CP_WAIT(NSTAGE - 2);
        __syncthreads();
        if (c + NSTAGE - 1 < KS) issue(c + NSTAGE - 1);
        CP_COMMIT();

        const char* bufA = smem + (c % NSTAGE) * STAGE_BYTES;
        const char* bufB = bufA + 16384;
        #pragma unroll
        for (int kk = 0; kk < 4; kk++) {      // four k16 chunks per stage
            int4 av[4];
            int2 bv[4];
            #pragma unroll
            for (int i = 0; i < 4; i++)
                av[i] = *(const int4*)(bufA + (((kk * 8 + wm * 4 + i) * 32 + lane) << 4));
            #pragma unroll
            for (int j = 0; j < 4; j++)
                bv[j] = *(const int2*)(bufB + (((kk * 16 + wn * 4 + j) * 32 + lane) << 3));
            #pragma unroll
            for (int i = 0; i < 4; i++)
                #pragma unroll
                for (int j = 0; j < 4; j++)
                    HMMA(acc[i][j], av[i], bv[j]);
        }
    }

    // epilogue: route output (DUAL: gate vs up region), scale + bias (+ absmax)
    const float* bias = bias0;
    float* C = C0;
    int sb = sb0, slot = 4, nt = ntile;
    if (DUAL && ntile >= NSPLIT) {
        bias = bias1; C = C1; sb = sb1; slot = 5; nt = ntile - NSPLIT;
    }
    const float sab = get_scale(sa) * get_scale(sb);
    const int g = lane >> 2, t = lane & 3;
    float vmax = 0.0f;
    #pragma unroll
    for (int i = 0; i < 4; i++) {
        int row0 = mtile * 128 + wm * 64 + i * 16 + g;
        #pragma unroll
        for (int j = 0; j < 4; j++) {
            int col = nt * 128 + wn * 32 + j * 8 + t * 2;
            if (col < Nvalid) {
                float b0 = __ldg(&bias[col]), b1 = __ldg(&bias[col + 1]);
                float2 v0, v1;
                v0.x = fmaf(acc[i][j][0], sab, b0);
                v0.y = fmaf(acc[i][j][1], sab, b1);
                v1.x = fmaf(acc[i][j][2], sab, b0);
                v1.y = fmaf(acc[i][j][3], sab, b1);
                *(float2*)(C + (size_t)row0 * Cstride + col) = v0;
                *(float2*)(C + (size_t)(row0 + 8) * Cstride + col) = v1;
                if (DUAL)
                    vmax = fmaxf(vmax, fmaxf(fmaxf(fabsf(v0.x), fabsf(v0.y)),
                                             fmaxf(fabsf(v1.x), fabsf(v1.y))));
            }
        }
    }
    if (DUAL) {
        #pragma unroll
        for (int o = 16; o; o >>= 1) vmax = fmaxf(vmax, __shfl_xor_sync(0xffffffffu, vmax, o));
        if (lane == 0) atomicMaxPosF(&g_absmax[slot], vmax);
    }
}

// ---------------- launch ----------------
extern "C" void kernel_launch(void* const* d_in, const int* in_sizes, int n_in,
                              void* d_out, int out_size) {
    (void)in_sizes; (void)n_in; (void)out_size;
    const float* x  = (const float*)d_in[0];
    const float* wg = (const float*)d_in[1];
    const float* wu = (const float*)d_in[2];
    const float* wd = (const float*)d_in[3];
    const float* bg = (const float*)d_in[4];
    const float* bu = (const float*)d_in[5];
    const float* bd = (const float*)d_in[6];
    float* out = (float*)d_out;

    __nv_bfloat16 *pXbf, *pGUbf, *pDbf, *pAbf;
    float *pGate, *pUp;
    cudaGetSymbolAddress((void**)&pXbf, g_Xbf);
    cudaGetSymbolAddress((void**)&pGUbf, g_GUbf);
    cudaGetSymbolAddress((void**)&pDbf, g_Dbf);
    cudaGetSymbolAddress((void**)&pAbf, g_Abf);
    cudaGetSymbolAddress((void**)&pGate, g_gate);
    cudaGetSymbolAddress((void**)&pUp, g_up);

    cudaFuncSetAttribute(k_gemm<true>,  cudaFuncAttributeMaxDynamicSharedMemorySize, NSTAGE * STAGE_BYTES);
    cudaFuncSetAttribute(k_gemm<false>, cudaFuncAttributeMaxDynamicSharedMemorySize, NSTAGE * STAGE_BYTES);

    const int RT = 256;
    const int nK32g = DMODEL / 32;   // 128
    const int nK32d = HPADK / 32;    // 342

    dim3 g1(TOKENS / 128, 2 * NSPLIT);    // 32 x 172: mtile fast, fused gate|up
    dim3 g2(TOKENS / 128, DMODEL / 128);  // 32 x 32

    // ncu captures launch index 3 -> fused gate/up GEMM there
    k_init<<<1, 8>>>();                                                        // 0
    k_absmax_all<<<2048, RT>>>(x, wg, wu, wd);                                 // 1
    k_pack_xgu<<<4096, RT>>>(x, pXbf, wg, wu, pGUbf);                          // 2
    k_gemm<true><<<g1, 256, NSTAGE * STAGE_BYTES>>>(                           // 3  <- ncu capture
        pXbf, pGUbf, bg, bu, pGate, pUp, nK32g, HIDDEN, HPADK, 0, 1, 2);
    k_packB_bf16<<<((size_t)DMODEL * nK32d + RT - 1) / RT, RT>>>(              // 4
        wd, pDbf, DMODEL, nK32d, HIDDEN, DMODEL, HIDDEN, 3);
    k_act<<<2048, RT>>>(pGate, pUp, (size_t)TOKENS * HPADK / 4);               // 5
    k_packA_bf16<<<((size_t)TOKENS * nK32d + RT - 1) / RT, RT>>>(              // 6
        pGate, pAbf, TOKENS, nK32d, HPADK, HPADK, 6);
    k_gemm<false><<<g2, 256, NSTAGE * STAGE_BYTES>>>(                          // 7
        pAbf, pDbf, bd, bd, out, out, nK32d, DMODEL, DMODEL, 6, 3, 3);
}

// round 14
// speedup vs baseline: 1.7329x; 1.0061x over previous
#include <cuda_runtime.h>
#include <cuda_bf16.h>
#include <cstdint>
#include <math.h>

#define TOKENS 4096
#define DMODEL 4096
#define HIDDEN 10922
#define HPADN  11008   // hidden padded to 128 (output cols for gate & up)
#define HPADK  10944   // hidden padded to 64; also activation buffer stride (mult of 4)
#define NSPLIT 86      // gate tiles 0..85, up tiles 86..171 in fused B buffer
#define NSTAGE 3       // pipeline stages, each K=64 (A 16KB + B 16KB = 32KB)
#define STAGE_BYTES 32768

// ---------------- device scratch (all bf16 frag-packed for HMMA) ----------------
__device__ __align__(256) __nv_bfloat16 g_Xbf[(size_t)TOKENS * DMODEL];       // A frags
__device__ __align__(256) __nv_bfloat16 g_GUbf[2 * (size_t)HPADN * DMODEL];   // B frags: wg | wu
__device__ __align__(256) __nv_bfloat16 g_Dbf[(size_t)DMODEL * HPADK];        // B frags
__device__ __align__(256) __nv_bfloat16 g_Abf[(size_t)TOKENS * HPADK];        // A frags
__device__ __align__(16) float g_gate[(size_t)TOKENS * HPADK];   // padded stride
__device__ __align__(16) float g_up  [(size_t)TOKENS * HPADK];   // padded stride
__device__ float g_absmax[8];   // 0:x 1:wg 2:wu 3:wd 4:gate 5:up 6:act

// ---------------- helpers ----------------
__device__ __forceinline__ void atomicMaxPosF(float* a, float v) {
    atomicMax((unsigned int*)a, __float_as_uint(v));
}
// quantize with precomputed reciprocal scale (mul instead of div)
__device__ __forceinline__ float quant_round_rs(float x, float rs) {
    float r = rintf(x * rs);
    return fminf(fmaxf(r, -127.0f), 127.0f);
}
__device__ __forceinline__ float get_scale(int slot) {
    return fmaxf(__fdiv_rn(g_absmax[slot], 127.0f), 1e-8f);
}
__device__ __forceinline__ float get_rscale(int slot) {
    return __fdiv_rn(1.0f, get_scale(slot));
}
__device__ __forceinline__ uint32_t smem_u32(const void* p) {
    uint32_t a;
    asm("{ .reg .u64 t; cvta.to.shared.u64 t, %1; cvt.u32.u64 %0, t; }" : "=r"(a) : "l"(p));
    return a;
}
__device__ __forceinline__ uint32_t bf2(float a, float b, float rs) {
    __nv_bfloat16 lo = __float2bfloat16_rn(quant_round_rs(a, rs));
    __nv_bfloat16 hi = __float2bfloat16_rn(quant_round_rs(b, rs));
    return (uint32_t)__bfloat16_as_ushort(lo) | ((uint32_t)__bfloat16_as_ushort(hi) << 16);
}
// load 32 consecutive floats; p at least 8B-aligned; a16: 16B-aligned
__device__ __forceinline__ void load32(const float* __restrict__ p, float* f, bool a16) {
    if (a16) {
        #pragma unroll
        for (int q = 0; q < 8; q++) *(float4*)&f[q * 4] = __ldg((const float4*)p + q);
    } else {
        #pragma unroll
        for (int q = 0; q < 16; q++) *(float2*)&f[q * 2] = __ldg((const float2*)p + q);
    }
}
#define CP_ASYNC16(dst, src) \
    asm volatile("cp.async.cg.shared.global [%0], [%1], 16;" :: "r"(dst), "l"(src))
#define CP_COMMIT() asm volatile("cp.async.commit_group;")
#define CP_WAIT(n)  asm volatile("cp.async.wait_group %0;" :: "n"(n))

#define HMMA(acc, a, b) \
    asm volatile("mma.sync.aligned.m16n8k16.row.col.f32.bf16.bf16.f32 " \
        "{%0,%1,%2,%3}, {%4,%5,%6,%7}, {%8,%9}, {%0,%1,%2,%3};" \
        : "+f"((acc)[0]), "+f"((acc)[1]), "+f"((acc)[2]), "+f"((acc)[3]) \
        : "r"((a).x), "r"((a).y), "r"((a).z), "r"((a).w), "r"((b).x), "r"((b).y))

__global__ void k_init() { if (threadIdx.x < 8) g_absmax[threadIdx.x] = 0.0f; }

// ---- one kernel: absmax of all 4 inputs; block-level reduce -> 1 atomic/block/seg ----
__device__ __forceinline__ void absmax_seg(const float* __restrict__ t, size_t n4, int slot,
                                           float* red) {
    float m = 0.0f;
    size_t i = (size_t)blockIdx.x * blockDim.x + threadIdx.x;
    size_t st = (size_t)gridDim.x * blockDim.x;
    const float4* t4 = (const float4*)t;
    for (; i < n4; i += st) {
        float4 v = t4[i];
        m = fmaxf(m, fmaxf(fmaxf(fabsf(v.x), fabsf(v.y)), fmaxf(fabsf(v.z), fabsf(v.w))));
    }
    #pragma unroll
    for (int o = 16; o; o >>= 1) m = fmaxf(m, __shfl_xor_sync(0xffffffffu, m, o));
    int wid = threadIdx.x >> 5, nw = blockDim.x >> 5;
    if ((threadIdx.x & 31) == 0) red[wid] = m;
    __syncthreads();
    if (wid == 0) {
        float v = (threadIdx.x < (unsigned)nw) ? red[threadIdx.x] : 0.0f;
        #pragma unroll
        for (int o = 16; o; o >>= 1) v = fmaxf(v, __shfl_xor_sync(0xffffffffu, v, o));
        if (threadIdx.x == 0) atomicMaxPosF(&g_absmax[slot], v);
    }
    __syncthreads();
}
__global__ void k_absmax_all(const float* __restrict__ x, const float* __restrict__ wg,
                             const float* __restrict__ wu, const float* __restrict__ wd) {
    __shared__ float red[32];
    absmax_seg(x,  (size_t)TOKENS * DMODEL / 4, 0, red);
    absmax_seg(wg, (size_t)HIDDEN * DMODEL / 4, 1, red);
    absmax_seg(wu, (size_t)HIDDEN * DMODEL / 4, 2, red);
    absmax_seg(wd, (size_t)DMODEL * HIDDEN / 4, 3, red);
}

// ======== bf16 HMMA pack bodies (m16n8k16) ========
// A frag layout: [mtile][k16][m16][lane]x16B (regs a0..a3)
__device__ __forceinline__ void packA_body(const float* __restrict__ src,
                                           uint32_t* __restrict__ d32, float rs,
                                           int rows, int nK32, int srcStride, int Kvalid,
                                           size_t gid, size_t gstride) {
    const int nK16 = nK32 * 2;
    size_t total = (size_t)rows * nK32;
    for (size_t i = gid; i < total; i += gstride) {
        int row = (int)(i % rows);
        int k32 = (int)(i / rows);
        int kb0 = k32 * 32;
        float f[32];
        if (kb0 + 32 <= Kvalid) {
            load32(src + (size_t)row * srcStride + kb0, f, true);
        } else {
            #pragma unroll
            for (int j = 0; j < 32; j++)
                f[j] = (kb0 + j < Kvalid) ? __ldg(src + (size_t)row * srcStride + kb0 + j) : 0.0f;
        }
        int mtile = row >> 7, rr = row & 127;
        int m16 = rr >> 4, g = rr & 7, rb = (rr >> 3) & 1;
        #pragma unroll
        for (int kh = 0; kh < 2; kh++) {
            int k16 = k32 * 2 + kh;
            uint32_t* base = d32 + (size_t)(mtile * nK16 + k16) * 1024 + m16 * 128 + 16 * g;
            const float* fk = f + kh * 16;
            #pragma unroll
            for (int t = 0; t < 4; t++) {
                base[4 * t + rb]     = bf2(fk[2 * t],     fk[2 * t + 1], rs);
                base[4 * t + rb + 2] = bf2(fk[8 + 2 * t], fk[9 + 2 * t], rs);
            }
        }
    }
}

// B frag layout: [ntile128][k16][n8][lane]x8B (regs b0,b1); 8 contiguous words per thread
__device__ __forceinline__ void packB_body(const float* __restrict__ src,
                                           uint32_t* __restrict__ d32, float rs,
                                           int rows, int nK32, int srcStride,
                                           int Nvalid, int Kvalid,
                                           size_t gid, size_t gstride) {
    const int nK16 = nK32 * 2;
    size_t total = (size_t)rows * nK32;
    for (size_t i = gid; i < total; i += gstride) {
        int n = (int)(i % rows);
        int k32 = (int)(i / rows);
        int kb0 = k32 * 32;
        float f[32];
        if (n < Nvalid) {
            size_t off = (size_t)n * srcStride + kb0;
            if (kb0 + 32 <= Kvalid) {
                load32(src + off, f, (off & 3) == 0);
            } else {
                #pragma unroll
                for (int j = 0; j < 32; j++)
                    f[j] = (kb0 + j < Kvalid) ? __ldg(src + off + j) : 0.0f;
            }
        } else {
            #pragma unroll
            for (int j = 0; j < 32; j++) f[j] = 0.0f;
        }
        int ntile = n >> 7, nr = n & 127;
        int n8 = nr >> 3, g = nr & 7;
        #pragma unroll
        for (int kh = 0; kh < 2; kh++) {
            int k16 = k32 * 2 + kh;
            uint32_t* base = d32 + (size_t)(ntile * nK16 + k16) * 1024 + n8 * 64 + 8 * g;
            const float* fk = f + kh * 16;
            uint32_t out[8];
            #pragma unroll
            for (int t = 0; t < 4; t++) {
                out[2 * t]     = bf2(fk[2 * t],     fk[2 * t + 1], rs);
                out[2 * t + 1] = bf2(fk[8 + 2 * t], fk[9 + 2 * t], rs);
            }
            *(uint4*)base       = *(const uint4*)&out[0];
            *(uint4*)(base + 4) = *(const uint4*)&out[4];
        }
    }
}

__global__ void k_packA_bf16(const float* __restrict__ src, __nv_bfloat16* __restrict__ dst,
                             int rows, int nK32, int srcStride, int Kvalid, int slot) {
    packA_body(src, (uint32_t*)dst, get_rscale(slot), rows, nK32, srcStride, Kvalid,
               (size_t)blockIdx.x * blockDim.x + threadIdx.x,
               (size_t)gridDim.x * blockDim.x);
}
__global__ void k_packB_bf16(const float* __restrict__ src, __nv_bfloat16* __restrict__ dst,
                             int rows, int nK32, int srcStride, int Nvalid, int Kvalid, int slot) {
    packB_body(src, (uint32_t*)dst, get_rscale(slot), rows, nK32, srcStride, Nvalid, Kvalid,
               (size_t)blockIdx.x * blockDim.x + threadIdx.x,
               (size_t)gridDim.x * blockDim.x);
}

// merged: packA(x) + packB(wg) + packB(wu) in one launch (gate/up GEMM is launch index 3)
__global__ void k_pack_xgu(const float* __restrict__ x, __nv_bfloat16* __restrict__ dx,
                           const float* __restrict__ wg, const float* __restrict__ wu,
                           __nv_bfloat16* __restrict__ dgu) {
    size_t gid = (size_t)blockIdx.x * blockDim.x + threadIdx.x;
    size_t gstride = (size_t)gridDim.x * blockDim.x;
    packA_body(x, (uint32_t*)dx, get_rscale(0), TOKENS, DMODEL / 32, DMODEL, DMODEL,
               gid, gstride);
    packB_body(wg, (uint32_t*)dgu, get_rscale(1), HPADN, DMODEL / 32, DMODEL, HIDDEN, DMODEL,
               gid, gstride);
    packB_body(wu, (uint32_t*)(dgu + (size_t)HPADN * DMODEL), get_rscale(2),
               HPADN, DMODEL / 32, DMODEL, HIDDEN, DMODEL, gid, gstride);
}

// ---- act = silu(q(gate)) * q(up) in place into gate; absmax -> slot 6 ----
__global__ void k_act(float* __restrict__ gate, const float* __restrict__ up, size_t n4) {
    float sg = get_scale(4), su = get_scale(5);
    float rsg = __fdiv_rn(1.0f, sg), rsu = __fdiv_rn(1.0f, su);
    float m = 0.0f;
    size_t i = (size_t)blockIdx.x * blockDim.x + threadIdx.x;
    size_t st = (size_t)gridDim.x * blockDim.x;
    float4* g4 = (float4*)gate;
    const float4* u4 = (const float4*)up;
    for (; i < n4; i += st) {
        float4 gv = g4[i];
        float4 uv = u4[i];
        float* gp = (float*)&gv;
        const float* uq4 = (const float*)&uv;
        #pragma unroll
        for (int k = 0; k < 4; k++) {
            float gq = quant_round_rs(gp[k], rsg) * sg;
            float uq = quant_round_rs(uq4[k], rsu) * su;
            float a = gq * (1.0f / (1.0f + expf(-gq))) * uq;
            gp[k] = a;
            m = fmaxf(m, fabsf(a));
        }
        g4[i] = gv;
    }
    __shared__ float red[32];
    #pragma unroll
    for (int o = 16; o; o >>= 1) m = fmaxf(m, __shfl_xor_sync(0xffffffffu, m, o));
    int wid = threadIdx.x >> 5, nw = blockDim.x >> 5;
    if ((threadIdx.x & 31) == 0) red[wid] = m;
    __syncthreads();
    if (wid == 0) {
        float v = (threadIdx.x < (unsigned)nw) ? red[threadIdx.x] : 0.0f;
        #pragma unroll
        for (int o = 16; o; o >>= 1) v = fmaxf(v, __shfl_xor_sync(0xffffffffu, v, o));
        if (threadIdx.x == 0) atomicMaxPosF(&g_absmax[6], v);
    }
}

// ---------------- bf16 HMMA GEMM (128x128, 8 warps, 64x32 warp tile) ----------------
// One stage = 32KB = K64 (4 k16-chunks): A 16KB + B 16KB. Per-tile operand stride = KS*16384 bytes.
// Grid: blockIdx.x = mtile (FAST axis -> B stripes hit DRAM once; A stays L2-resident).
// DUAL: B holds gate tiles [0,NSPLIT) then up tiles [NSPLIT,2*NSPLIT); epilogue routes by ntile.
template<bool DUAL>
__global__ void __launch_bounds__(256, 2)
k_gemm(const __nv_bfloat16* __restrict__ A, const __nv_bfloat16* __restrict__ B,
       const float* __restrict__ bias0, const float* __restrict__ bias1,
       float* __restrict__ C0, float* __restrict__ C1,
       int nK32, int Nvalid, int Cstride, int sa, int sb0, int sb1) {
    extern __shared__ __align__(16) char smem[];   // NSTAGE * 32KB
    const int tid = threadIdx.x, lane = tid & 31, wid = tid >> 5;
    const int wm = wid >> 2, wn = wid & 3;         // warp grid 2 x 4 (64x32 warp tile)
    const int mtile = blockIdx.x, ntile = blockIdx.y;   // m fastest for wave locality

    const int KS = nK32 >> 1;                       // stages (K=64 each); nK32 always even
    const char* Ag = (const char*)A + (size_t)mtile * KS * 16384;
    const char* Bg = (const char*)B + (size_t)ntile * KS * 16384;

    float acc[4][4][4];
    #pragma unroll
    for (int i = 0; i < 4; i++)
        #pragma unroll
        for (int j = 0; j < 4; j++)
            #pragma unroll
            for (int r = 0; r < 4; r++) acc[i][j][r] = 0.0f;

    const uint32_t sbase = smem_u32(smem);
    const uint32_t co = (uint32_t)tid * 16u;

    auto issue = [&](int st) {
        uint32_t buf = sbase + (uint32_t)(st % NSTAGE) * (uint32_t)STAGE_BYTES;
        const char* ga = Ag + (size_t)st * 16384;
        const char* gb = Bg + (size_t)st * 16384;
        #pragma unroll
        for (int w = 0; w < 4; w++) {
            CP_ASYNC16(buf + co + w * 4096u,          ga + co + w * 4096u);
            CP_ASYNC16(buf + co + w * 4096u + 16384u, gb + co + w * 4096u);
        }
    };

    #pragma unroll
    for (int p = 0; p < NSTAGE - 1; p++) {
        if (p < KS) issue(p);
        CP_COMMIT();
    }

    for (int c = 0; c < KS; c++) {
        CP_WAIT(NSTAGE - 2);
        __syncthreads();
        if (c + NSTAGE - 1 < KS) issue(c + NSTAGE - 1);
        CP_COMMIT();

        const char* bufA = smem + (c % NSTAGE) * STAGE_BYTES;
        const char* bufB = bufA + 16384;
        #pragma unroll
        for (int kk = 0; kk < 4; kk++) {      // four k16 chunks per stage
            int4 av[4];
            int2 bv[4];
            #pragma unroll
            for (int i = 0; i < 4; i++)
                av[i] = *(const int4*)(bufA + (((kk * 8 + wm * 4 + i) * 32 + lane) << 4));
            #pragma unroll
            for (int j = 0; j < 4; j++)
                bv[j] = *(const int2*)(bufB + (((kk * 16 + wn * 4 + j) * 32 + lane) << 3));
            #pragma unroll
            for (int i = 0; i < 4; i++)
                #pragma unroll
                for (int j = 0; j < 4; j++)
                    HMMA(acc[i][j], av[i], bv[j]);
        }
    }

    // epilogue: route output (DUAL: gate vs up region), scale + bias (+ absmax)
    const float* bias = bias0;
    float* C = C0;
    int sb = sb0, slot = 4, nt = ntile;
    if (DUAL && ntile >= NSPLIT) {
        bias = bias1; C = C1; sb = sb1; slot = 5; nt = ntile - NSPLIT;
    }
    const float sab = get_scale(sa) * get_scale(sb);
    const int g = lane >> 2, t = lane & 3;
    float vmax = 0.0f;
    #pragma unroll
    for (int i = 0; i < 4; i++) {
        int row0 = mtile * 128 + wm * 64 + i * 16 + g;
        #pragma unroll
        for (int j = 0; j < 4; j++) {
            int col = nt * 128 + wn * 32 + j * 8 + t * 2;
            if (col < Nvalid) {
                float b0 = __ldg(&bias[col]), b1 = __ldg(&bias[col + 1]);
                float2 v0, v1;
                v0.x = fmaf(acc[i][j][0], sab, b0);
                v0.y = fmaf(acc[i][j][1], sab, b1);
                v1.x = fmaf(acc[i][j][2], sab, b0);
                v1.y = fmaf(acc[i][j][3], sab, b1);
                *(float2*)(C + (size_t)row0 * Cstride + col) = v0;
                *(float2*)(C + (size_t)(row0 + 8) * Cstride + col) = v1;
                if (DUAL)
                    vmax = fmaxf(vmax, fmaxf(fmaxf(fabsf(v0.x), fabsf(v0.y)),
                                             fmaxf(fabsf(v1.x), fabsf(v1.y))));
            }
        }
    }
    if (DUAL) {
        #pragma unroll
        for (int o = 16; o; o >>= 1) vmax = fmaxf(vmax, __shfl_xor_sync(0xffffffffu, vmax, o));
        if (lane == 0) atomicMaxPosF(&g_absmax[slot], vmax);
    }
}

// ---------------- launch ----------------
extern "C" void kernel_launch(void* const* d_in, const int* in_sizes, int n_in,
                              void* d_out, int out_size) {
    (void)in_sizes; (void)n_in; (void)out_size;
    const float* x  = (const float*)d_in[0];
    const float* wg = (const float*)d_in[1];
    const float* wu = (const float*)d_in[2];
    const float* wd = (const float*)d_in[3];
    const float* bg = (const float*)d_in[4];
    const float* bu = (const float*)d_in[5];
    const float* bd = (const float*)d_in[6];
    float* out = (float*)d_out;

    __nv_bfloat16 *pXbf, *pGUbf, *pDbf, *pAbf;
    float *pGate, *pUp;
    cudaGetSymbolAddress((void**)&pXbf, g_Xbf);
    cudaGetSymbolAddress((void**)&pGUbf, g_GUbf);
    cudaGetSymbolAddress((void**)&pDbf, g_Dbf);
    cudaGetSymbolAddress((void**)&pAbf, g_Abf);
    cudaGetSymbolAddress((void**)&pGate, g_gate);
    cudaGetSymbolAddress((void**)&pUp, g_up);

    cudaFuncSetAttribute(k_gemm<true>,  cudaFuncAttributeMaxDynamicSharedMemorySize, NSTAGE * STAGE_BYTES);
    cudaFuncSetAttribute(k_gemm<false>, cudaFuncAttributeMaxDynamicSharedMemorySize, NSTAGE * STAGE_BYTES);

    const int RT = 256;
    const int nK32g = DMODEL / 32;   // 128
    const int nK32d = HPADK / 32;    // 342

    dim3 g1(TOKENS / 128, 2 * NSPLIT);    // 32 x 172: mtile fast, fused gate|up
    dim3 g2(TOKENS / 128, DMODEL / 128);  // 32 x 32

    // ncu captures launch index 3 -> fused gate/up GEMM there
    k_init<<<1, 8>>>();                                                        // 0
    k_absmax_all<<<1024, 512>>>(x, wg, wu, wd);                                // 1
    k_pack_xgu<<<4096, RT>>>(x, pXbf, wg, wu, pGUbf);                          // 2
    k_gemm<true><<<g1, 256, NSTAGE * STAGE_BYTES>>>(                           // 3  <- ncu capture
        pXbf, pGUbf, bg, bu, pGate, pUp, nK32g, HIDDEN, HPADK, 0, 1, 2);
    k_packB_bf16<<<((size_t)DMODEL * nK32d + RT - 1) / RT, RT>>>(              // 4
        wd, pDbf, DMODEL, nK32d, HIDDEN, DMODEL, HIDDEN, 3);
    k_act<<<1024, 512>>>(pGate, pUp, (size_t)TOKENS * HPADK / 4);              // 5
    k_packA_bf16<<<((size_t)TOKENS * nK32d + RT - 1) / RT, RT>>>(              // 6
        pGate, pAbf, TOKENS, nK32d, HPADK, HPADK, 6);
    k_gemm<false><<<g2, 256, NSTAGE * STAGE_BYTES>>>(                          // 7
        pAbf, pDbf, bd, bd, out, out, nK32d, DMODEL, DMODEL, 6, 3, 3);
}

// round 15
// speedup vs baseline: 1.7355x; 1.0015x over previous
#include <cuda_runtime.h>
#include <cuda_bf16.h>
#include <cstdint>
#include <math.h>

#define TOKENS 4096
#define DMODEL 4096
#define HIDDEN 10922
#define HPADN  11008   // hidden padded to 128 (output cols for gate & up)
#define HPADK  10944   // hidden padded to 64; also activation buffer stride (mult of 4)
#define NSPLIT 86      // gate tiles 0..85, up tiles 86..171 in fused B buffer
#define NSTAGE 3       // pipeline stages, each K=64 (A 16KB + B 16KB = 32KB)
#define STAGE_BYTES 32768

// ---------------- device scratch (all bf16 frag-packed for HMMA) ----------------
__device__ __align__(256) __nv_bfloat16 g_Xbf[(size_t)TOKENS * DMODEL];       // A frags
__device__ __align__(256) __nv_bfloat16 g_GUbf[2 * (size_t)HPADN * DMODEL];   // B frags: wg | wu
__device__ __align__(256) __nv_bfloat16 g_Dbf[(size_t)DMODEL * HPADK];        // B frags
__device__ __align__(256) __nv_bfloat16 g_Abf[(size_t)TOKENS * HPADK];        // A frags
__device__ __align__(16) float g_gate[(size_t)TOKENS * HPADK];   // padded stride
__device__ __align__(16) float g_up  [(size_t)TOKENS * HPADK];   // padded stride
__device__ float g_absmax[8];   // 0:x 1:wg 2:wu 3:wd 4:gate 5:up 6:act

// ---------------- helpers ----------------
__device__ __forceinline__ void atomicMaxPosF(float* a, float v) {
    atomicMax((unsigned int*)a, __float_as_uint(v));
}
__device__ __forceinline__ float quant_round_rs(float x, float rs) {
    float r = rintf(x * rs);
    return fminf(fmaxf(r, -127.0f), 127.0f);
}
__device__ __forceinline__ float get_scale(int slot) {
    return fmaxf(__fdiv_rn(g_absmax[slot], 127.0f), 1e-8f);
}
__device__ __forceinline__ float get_rscale(int slot) {
    return __fdiv_rn(1.0f, get_scale(slot));
}
__device__ __forceinline__ uint32_t smem_u32(const void* p) {
    uint32_t a;
    asm("{ .reg .u64 t; cvta.to.shared.u64 t, %1; cvt.u32.u64 %0, t; }" : "=r"(a) : "l"(p));
    return a;
}
__device__ __forceinline__ uint32_t bf2(float a, float b, float rs) {
    __nv_bfloat16 lo = __float2bfloat16_rn(quant_round_rs(a, rs));
    __nv_bfloat16 hi = __float2bfloat16_rn(quant_round_rs(b, rs));
    return (uint32_t)__bfloat16_as_ushort(lo) | ((uint32_t)__bfloat16_as_ushort(hi) << 16);
}
// load 32 consecutive floats; p at least 8B-aligned; a16: 16B-aligned
__device__ __forceinline__ void load32(const float* __restrict__ p, float* f, bool a16) {
    if (a16) {
        #pragma unroll
        for (int q = 0; q < 8; q++) *(float4*)&f[q * 4] = __ldg((const float4*)p + q);
    } else {
        #pragma unroll
        for (int q = 0; q < 16; q++) *(float2*)&f[q * 2] = __ldg((const float2*)p + q);
    }
}
#define CP_ASYNC16(dst, src) \
    asm volatile("cp.async.cg.shared.global [%0], [%1], 16;" :: "r"(dst), "l"(src))
#define CP_COMMIT() asm volatile("cp.async.commit_group;")
#define CP_WAIT(n)  asm volatile("cp.async.wait_group %0;" :: "n"(n))

#define HMMA(acc, a, b) \
    asm volatile("mma.sync.aligned.m16n8k16.row.col.f32.bf16.bf16.f32 " \
        "{%0,%1,%2,%3}, {%4,%5,%6,%7}, {%8,%9}, {%0,%1,%2,%3};" \
        : "+f"((acc)[0]), "+f"((acc)[1]), "+f"((acc)[2]), "+f"((acc)[3]) \
        : "r"((a).x), "r"((a).y), "r"((a).z), "r"((a).w), "r"((b).x), "r"((b).y))

__global__ void k_init() { if (threadIdx.x < 8) g_absmax[threadIdx.x] = 0.0f; }

// ---- one kernel: absmax of all 4 inputs; block-level reduce -> 1 atomic/block/seg ----
__device__ __forceinline__ void absmax_seg(const float* __restrict__ t, size_t n4, int slot,
                                           float* red) {
    float m = 0.0f;
    size_t i = (size_t)blockIdx.x * blockDim.x + threadIdx.x;
    size_t st = (size_t)gridDim.x * blockDim.x;
    const float4* t4 = (const float4*)t;
    for (; i < n4; i += st) {
        float4 v = t4[i];
        m = fmaxf(m, fmaxf(fmaxf(fabsf(v.x), fabsf(v.y)), fmaxf(fabsf(v.z), fabsf(v.w))));
    }
    #pragma unroll
    for (int o = 16; o; o >>= 1) m = fmaxf(m, __shfl_xor_sync(0xffffffffu, m, o));
    int wid = threadIdx.x >> 5, nw = blockDim.x >> 5;
    if ((threadIdx.x & 31) == 0) red[wid] = m;
    __syncthreads();
    if (wid == 0) {
        float v = (threadIdx.x < (unsigned)nw) ? red[threadIdx.x] : 0.0f;
        #pragma unroll
        for (int o = 16; o; o >>= 1) v = fmaxf(v, __shfl_xor_sync(0xffffffffu, v, o));
        if (threadIdx.x == 0) atomicMaxPosF(&g_absmax[slot], v);
    }
    __syncthreads();
}
__global__ void k_absmax_all(const float* __restrict__ x, const float* __restrict__ wg,
                             const float* __restrict__ wu, const float* __restrict__ wd) {
    __shared__ float red[32];
    absmax_seg(x,  (size_t)TOKENS * DMODEL / 4, 0, red);
    absmax_seg(wg, (size_t)HIDDEN * DMODEL / 4, 1, red);
    absmax_seg(wu, (size_t)HIDDEN * DMODEL / 4, 2, red);
    absmax_seg(wd, (size_t)DMODEL * HIDDEN / 4, 3, red);
}

// ======== bf16 HMMA pack bodies (m16n8k16) ========
// A frag layout: [mtile][k16][m16][lane]x16B (regs a0..a3)
__device__ __forceinline__ void packA_body(const float* __restrict__ src,
                                           uint32_t* __restrict__ d32, float rs,
                                           int rows, int nK32, int srcStride, int Kvalid,
                                           size_t gid, size_t gstride) {
    const int nK16 = nK32 * 2;
    size_t total = (size_t)rows * nK32;
    for (size_t i = gid; i < total; i += gstride) {
        int row = (int)(i % rows);
        int k32 = (int)(i / rows);
        int kb0 = k32 * 32;
        float f[32];
        if (kb0 + 32 <= Kvalid) {
            load32(src + (size_t)row * srcStride + kb0, f, true);
        } else {
            #pragma unroll
            for (int j = 0; j < 32; j++)
                f[j] = (kb0 + j < Kvalid) ? __ldg(src + (size_t)row * srcStride + kb0 + j) : 0.0f;
        }
        int mtile = row >> 7, rr = row & 127;
        int m16 = rr >> 4, g = rr & 7, rb = (rr >> 3) & 1;
        #pragma unroll
        for (int kh = 0; kh < 2; kh++) {
            int k16 = k32 * 2 + kh;
            uint32_t* base = d32 + (size_t)(mtile * nK16 + k16) * 1024 + m16 * 128 + 16 * g;
            const float* fk = f + kh * 16;
            #pragma unroll
            for (int t = 0; t < 4; t++) {
                base[4 * t + rb]     = bf2(fk[2 * t],     fk[2 * t + 1], rs);
                base[4 * t + rb + 2] = bf2(fk[8 + 2 * t], fk[9 + 2 * t], rs);
            }
        }
    }
}

// B frag layout: [ntile128][k16][n8][lane]x8B (regs b0,b1); 8 contiguous words per thread
__device__ __forceinline__ void packB_body(const float* __restrict__ src,
                                           uint32_t* __restrict__ d32, float rs,
                                           int rows, int nK32, int srcStride,
                                           int Nvalid, int Kvalid,
                                           size_t gid, size_t gstride) {
    const int nK16 = nK32 * 2;
    size_t total = (size_t)rows * nK32;
    for (size_t i = gid; i < total; i += gstride) {
        int n = (int)(i % rows);
        int k32 = (int)(i / rows);
        int kb0 = k32 * 32;
        float f[32];
        if (n < Nvalid) {
            size_t off = (size_t)n * srcStride + kb0;
            if (kb0 + 32 <= Kvalid) {
                load32(src + off, f, (off & 3) == 0);
            } else {
                #pragma unroll
                for (int j = 0; j < 32; j++)
                    f[j] = (kb0 + j < Kvalid) ? __ldg(src + off + j) : 0.0f;
            }
        } else {
            #pragma unroll
            for (int j = 0; j < 32; j++) f[j] = 0.0f;
        }
        int ntile = n >> 7, nr = n & 127;
        int n8 = nr >> 3, g = nr & 7;
        #pragma unroll
        for (int kh = 0; kh < 2; kh++) {
            int k16 = k32 * 2 + kh;
            uint32_t* base = d32 + (size_t)(ntile * nK16 + k16) * 1024 + n8 * 64 + 8 * g;
            const float* fk = f + kh * 16;
            uint32_t out[8];
            #pragma unroll
            for (int t = 0; t < 4; t++) {
                out[2 * t]     = bf2(fk[2 * t],     fk[2 * t + 1], rs);
                out[2 * t + 1] = bf2(fk[8 + 2 * t], fk[9 + 2 * t], rs);
            }
            *(uint4*)base       = *(const uint4*)&out[0];
            *(uint4*)(base + 4) = *(const uint4*)&out[4];
        }
    }
}

__global__ void k_packA_bf16(const float* __restrict__ src, __nv_bfloat16* __restrict__ dst,
                             int rows, int nK32, int srcStride, int Kvalid, int slot) {
    packA_body(src, (uint32_t*)dst, get_rscale(slot), rows, nK32, srcStride, Kvalid,
               (size_t)blockIdx.x * blockDim.x + threadIdx.x,
               (size_t)gridDim.x * blockDim.x);
}
__global__ void k_packB_bf16(const float* __restrict__ src, __nv_bfloat16* __restrict__ dst,
                             int rows, int nK32, int srcStride, int Nvalid, int Kvalid, int slot) {
    packB_body(src, (uint32_t*)dst, get_rscale(slot), rows, nK32, srcStride, Nvalid, Kvalid,
               (size_t)blockIdx.x * blockDim.x + threadIdx.x,
               (size_t)gridDim.x * blockDim.x);
}

// merged: packA(x) + packB(wg) + packB(wu) in one launch
__global__ void k_pack_xgu(const float* __restrict__ x, __nv_bfloat16* __restrict__ dx,
                           const float* __restrict__ wg, const float* __restrict__ wu,
                           __nv_bfloat16* __restrict__ dgu) {
    size_t gid = (size_t)blockIdx.x * blockDim.x + threadIdx.x;
    size_t gstride = (size_t)gridDim.x * blockDim.x;
    packA_body(x, (uint32_t*)dx, get_rscale(0), TOKENS, DMODEL / 32, DMODEL, DMODEL,
               gid, gstride);
    packB_body(wg, (uint32_t*)dgu, get_rscale(1), HPADN, DMODEL / 32, DMODEL, HIDDEN, DMODEL,
               gid, gstride);
    packB_body(wu, (uint32_t*)(dgu + (size_t)HPADN * DMODEL), get_rscale(2),
               HPADN, DMODEL / 32, DMODEL, HIDDEN, DMODEL, gid, gstride);
}

// ---- act = silu(q(gate)) * q(up) in place into gate; absmax -> slot 6 ----
__global__ void k_act(float* __restrict__ gate, const float* __restrict__ up, size_t n4) {
    float sg = get_scale(4), su = get_scale(5);
    float rsg = __fdiv_rn(1.0f, sg), rsu = __fdiv_rn(1.0f, su);
    float m = 0.0f;
    size_t i = (size_t)blockIdx.x * blockDim.x + threadIdx.x;
    size_t st = (size_t)gridDim.x * blockDim.x;
    float4* g4 = (float4*)gate;
    const float4* u4 = (const float4*)up;
    for (; i < n4; i += st) {
        float4 gv = g4[i];
        float4 uv = u4[i];
        float* gp = (float*)&gv;
        const float* uq4 = (const float*)&uv;
        #pragma unroll
        for (int k = 0; k < 4; k++) {
            float gq = quant_round_rs(gp[k], rsg) * sg;
            float uq = quant_round_rs(uq4[k], rsu) * su;
            float a = gq * (1.0f / (1.0f + expf(-gq))) * uq;
            gp[k] = a;
            m = fmaxf(m, fabsf(a));
        }
        g4[i] = gv;
    }
    __shared__ float red[32];
    #pragma unroll
    for (int o = 16; o; o >>= 1) m = fmaxf(m, __shfl_xor_sync(0xffffffffu, m, o));
    int wid = threadIdx.x >> 5, nw = blockDim.x >> 5;
    if ((threadIdx.x & 31) == 0) red[wid] = m;
    __syncthreads();
    if (wid == 0) {
        float v = (threadIdx.x < (unsigned)nw) ? red[threadIdx.x] : 0.0f;
        #pragma unroll
        for (int o = 16; o; o >>= 1) v = fmaxf(v, __shfl_xor_sync(0xffffffffu, v, o));
        if (threadIdx.x == 0) atomicMaxPosF(&g_absmax[6], v);
    }
}

// ---------------- bf16 HMMA GEMM (128x128, 8 warps, 64x32 warp tile) ----------------
// One stage = 32KB = K64 (4 k16-chunks): A 16KB + B 16KB. Per-tile operand stride = KS*16384 bytes.
// Grid: blockIdx.x = mtile (FAST axis -> B stripes hit DRAM once; A stays L2-resident).
// DUAL: B holds gate tiles [0,NSPLIT) then up tiles [NSPLIT,2*NSPLIT); epilogue routes by ntile.
template<bool DUAL>
__global__ void __launch_bounds__(256, 2)
k_gemm(const __nv_bfloat16* __restrict__ A, const __nv_bfloat16* __restrict__ B,
       const float* __restrict__ bias0, const float* __restrict__ bias1,
       float* __restrict__ C0, float* __restrict__ C1,
       int nK32, int Nvalid, int Cstride, int sa, int sb0, int sb1) {
    extern __shared__ __align__(16) char smem[];   // NSTAGE * 32KB
    const int tid = threadIdx.x, lane = tid & 31, wid = tid >> 5;
    const int wm = wid >> 2, wn = wid & 3;         // warp grid 2 x 4 (64x32 warp tile)
    const int mtile = blockIdx.x, ntile = blockIdx.y;   // m fastest for wave locality

    const int KS = nK32 >> 1;                       // stages (K=64 each); nK32 always even
    const char* Ag = (const char*)A + (size_t)mtile * KS * 16384;
    const char* Bg = (const char*)B + (size_t)ntile * KS * 16384;

    float acc[4][4][4];
    #pragma unroll
    for (int i = 0; i < 4; i++)
        #pragma unroll
        for (int j = 0; j < 4; j++)
            #pragma unroll
            for (int r = 0; r < 4; r++) acc[i][j][r] = 0.0f;

    const uint32_t sbase = smem_u32(smem);
    const uint32_t co = (uint32_t)tid * 16u;

    auto issue = [&](int st) {
        uint32_t buf = sbase + (uint32_t)(st % NSTAGE) * (uint32_t)STAGE_BYTES;
        const char* ga = Ag + (size_t)st * 16384;
        const char* gb = Bg + (size_t)st * 16384;
        #pragma unroll
        for (int w = 0; w < 4; w++) {
            CP_ASYNC16(buf + co + w * 4096u,          ga + co + w * 4096u);
            CP_ASYNC16(buf + co + w * 4096u + 16384u, gb + co + w * 4096u);
        }
    };

    #pragma unroll
    for (int p = 0; p < NSTAGE - 1; p++) {
        if (p < KS) issue(p);
        CP_COMMIT();
    }

    for (int c = 0; c < KS; c++) {
        CP_WAIT(NSTAGE - 2);
        __syncthreads();
        if (c + NSTAGE - 1 < KS) issue(c + NSTAGE - 1);
        CP_COMMIT();

        const char* bufA = smem + (c % NSTAGE) * STAGE_BYTES;
        const char* bufB = bufA + 16384;
        #pragma unroll
        for (int kk = 0; kk < 4; kk++) {      // four k16 chunks per stage
            int4 av[4];
            int2 bv[4];
            #pragma unroll
            for (int i = 0; i < 4; i++)
                av[i] = *(const int4*)(bufA + (((kk * 8 + wm * 4 + i) * 32 + lane) << 4));
            #pragma unroll
            for (int j = 0; j < 4; j++)
                bv[j] = *(const int2*)(bufB + (((kk * 16 + wn * 4 + j) * 32 + lane) << 3));
            #pragma unroll
            for (int i = 0; i < 4; i++)
                #pragma unroll
                for (int j = 0; j < 4; j++)
                    HMMA(acc[i][j], av[i], bv[j]);
        }
    }

    // epilogue: route output (DUAL: gate vs up region), scale + bias (+ absmax)
    const float* bias = bias0;
    float* C = C0;
    int sb = sb0, slot = 4, nt = ntile;
    if (DUAL && ntile >= NSPLIT) {
        bias = bias1; C = C1; sb = sb1; slot = 5; nt = ntile - NSPLIT;
    }
    const float sab = get_scale(sa) * get_scale(sb);
    const int g = lane >> 2, t = lane & 3;
    float vmax = 0.0f;
    #pragma unroll
    for (int i = 0; i < 4; i++) {
        int row0 = mtile * 128 + wm * 64 + i * 16 + g;
        #pragma unroll
        for (int j = 0; j < 4; j++) {
            int col = nt * 128 + wn * 32 + j * 8 + t * 2;
            if (col < Nvalid) {
                float b0 = __ldg(&bias[col]), b1 = __ldg(&bias[col + 1]);
                float2 v0, v1;
                v0.x = fmaf(acc[i][j][0], sab, b0);
                v0.y = fmaf(acc[i][j][1], sab, b1);
                v1.x = fmaf(acc[i][j][2], sab, b0);
                v1.y = fmaf(acc[i][j][3], sab, b1);
                *(float2*)(C + (size_t)row0 * Cstride + col) = v0;
                *(float2*)(C + (size_t)(row0 + 8) * Cstride + col) = v1;
                if (DUAL)
                    vmax = fmaxf(vmax, fmaxf(fmaxf(fabsf(v0.x), fabsf(v0.y)),
                                             fmaxf(fabsf(v1.x), fabsf(v1.y))));
            }
        }
    }
    if (DUAL) {
        #pragma unroll
        for (int o = 16; o; o >>= 1) vmax = fmaxf(vmax, __shfl_xor_sync(0xffffffffu, vmax, o));
        if (lane == 0) atomicMaxPosF(&g_absmax[slot], vmax);
    }
}

// ---------------- launch ----------------
extern "C" void kernel_launch(void* const* d_in, const int* in_sizes, int n_in,
                              void* d_out, int out_size) {
    (void)in_sizes; (void)n_in; (void)out_size;
    const float* x  = (const float*)d_in[0];
    const float* wg = (const float*)d_in[1];
    const float* wu = (const float*)d_in[2];
    const float* wd = (const float*)d_in[3];
    const float* bg = (const float*)d_in[4];
    const float* bu = (const float*)d_in[5];
    const float* bd = (const float*)d_in[6];
    float* out = (float*)d_out;

    __nv_bfloat16 *pXbf, *pGUbf, *pDbf, *pAbf;
    float *pGate, *pUp;
    cudaGetSymbolAddress((void**)&pXbf, g_Xbf);
    cudaGetSymbolAddress((void**)&pGUbf, g_GUbf);
    cudaGetSymbolAddress((void**)&pDbf, g_Dbf);
    cudaGetSymbolAddress((void**)&pAbf, g_Abf);
    cudaGetSymbolAddress((void**)&pGate, g_gate);
    cudaGetSymbolAddress((void**)&pUp, g_up);

    cudaFuncSetAttribute(k_gemm<true>,  cudaFuncAttributeMaxDynamicSharedMemorySize, NSTAGE * STAGE_BYTES);
    cudaFuncSetAttribute(k_gemm<false>, cudaFuncAttributeMaxDynamicSharedMemorySize, NSTAGE * STAGE_BYTES);

    // side stream + fork/join events: created ONCE on the first (uncaptured,
    // correctness) call; during graph capture only record/wait are issued,
    // which are graph-capturable. No device memory is allocated here.
    static cudaStream_t s2 = nullptr;
    static cudaEvent_t evFork = nullptr, evJoin = nullptr;
    if (s2 == nullptr) {
        cudaStreamCreateWithFlags(&s2, cudaStreamNonBlocking);
        cudaEventCreateWithFlags(&evFork, cudaEventDisableTiming);
        cudaEventCreateWithFlags(&evJoin, cudaEventDisableTiming);
    }

    const int RT = 256;
    const int nK32g = DMODEL / 32;   // 128
    const int nK32d = HPADK / 32;    // 342

    dim3 g1(TOKENS / 128, 2 * NSPLIT);    // 32 x 172: mtile fast, fused gate|up
    dim3 g2(TOKENS / 128, DMODEL / 128);  // 32 x 32

    k_init<<<1, 8>>>();
    k_absmax_all<<<1024, 512>>>(x, wg, wu, wd);

    // fork: packB(wd) depends only on absmax; runs concurrent with pack_xgu + gate/up GEMM
    cudaEventRecord(evFork, 0);
    cudaStreamWaitEvent(s2, evFork, 0);
    k_packB_bf16<<<((size_t)DMODEL * nK32d + RT - 1) / RT, RT, 0, s2>>>(
        wd, pDbf, DMODEL, nK32d, HIDDEN, DMODEL, HIDDEN, 3);
    cudaEventRecord(evJoin, s2);

    // main stream: pack x/wg/wu, fused gate/up GEMM, act, pack act
    k_pack_xgu<<<4096, RT>>>(x, pXbf, wg, wu, pGUbf);
    k_gemm<true><<<g1, 256, NSTAGE * STAGE_BYTES>>>(
        pXbf, pGUbf, bg, bu, pGate, pUp, nK32g, HIDDEN, HPADK, 0, 1, 2);
    k_act<<<1024, 512>>>(pGate, pUp, (size_t)TOKENS * HPADK / 4);
    k_packA_bf16<<<((size_t)TOKENS * nK32d + RT - 1) / RT, RT>>>(
        pGate, pAbf, TOKENS, nK32d, HPADK, HPADK, 6);

    // join: down GEMM needs pDbf
    cudaStreamWaitEvent(0, evJoin, 0);
    k_gemm<false><<<g2, 256, NSTAGE * STAGE_BYTES>>>(
        pAbf, pDbf, bd, bd, out, out, nK32d, DMODEL, DMODEL, 6, 3, 3);
}